// round 10
// baseline (speedup 1.0000x reference)
#include <cuda_runtime.h>
#include <cuda_bf16.h>
#include <cstdint>

#define BATCH 4
#define SEQ   2048
#define EMB   1024
#define NH    16
#define HD    64
#define TOK   (BATCH*SEQ)      // 8192

// ---------------- scratch (device globals; allocation-free rule) ----------
__device__ __nv_bfloat16 g_xh[(size_t)TOK * EMB];
__device__ __nv_bfloat16 g_xl[(size_t)TOK * EMB];
__device__ __nv_bfloat16 g_wqh[(size_t)3 * EMB * EMB];
__device__ __nv_bfloat16 g_wql[(size_t)3 * EMB * EMB];
__device__ __nv_bfloat16 g_wph[(size_t)EMB * EMB];
__device__ __nv_bfloat16 g_wpl[(size_t)EMB * EMB];
__device__ __nv_bfloat16 g_qkvh[(size_t)TOK * 3 * EMB];
__device__ __nv_bfloat16 g_qkvl[(size_t)TOK * 3 * EMB];
__device__ __nv_bfloat16 g_atth[(size_t)TOK * EMB];
__device__ __nv_bfloat16 g_attl[(size_t)TOK * EMB];

// ---------------- primitives ----------------
__device__ __forceinline__ uint32_t smem_u32(const void* p) {
    uint32_t a;
    asm("{ .reg .u64 t; cvta.to.shared.u64 t, %1; cvt.u32.u64 %0, t; }" : "=r"(a) : "l"(p));
    return a;
}
__device__ __forceinline__ void ldm_x4(uint32_t* r, uint32_t addr) {
    asm volatile("ldmatrix.sync.aligned.m8n8.x4.shared.b16 {%0,%1,%2,%3}, [%4];"
        : "=r"(r[0]), "=r"(r[1]), "=r"(r[2]), "=r"(r[3]) : "r"(addr));
}
__device__ __forceinline__ void ldm_x4_t(uint32_t* r, uint32_t addr) {
    asm volatile("ldmatrix.sync.aligned.m8n8.x4.trans.shared.b16 {%0,%1,%2,%3}, [%4];"
        : "=r"(r[0]), "=r"(r[1]), "=r"(r[2]), "=r"(r[3]) : "r"(addr));
}
__device__ __forceinline__ void mma16816(float* c, const uint32_t* a, const uint32_t* b) {
    asm volatile(
        "mma.sync.aligned.m16n8k16.row.col.f32.bf16.bf16.f32 "
        "{%0,%1,%2,%3}, {%4,%5,%6,%7}, {%8,%9}, {%0,%1,%2,%3};"
        : "+f"(c[0]), "+f"(c[1]), "+f"(c[2]), "+f"(c[3])
        : "r"(a[0]), "r"(a[1]), "r"(a[2]), "r"(a[3]), "r"(b[0]), "r"(b[1]));
}
#define CP16(dst, src) \
    asm volatile("cp.async.cg.shared.global [%0], [%1], 16;" \
        :: "r"(dst), "l"(src) : "memory")
#define CP_COMMIT() asm volatile("cp.async.commit_group;" ::: "memory")
#define CP_WAIT0()  asm volatile("cp.async.wait_group 0;" ::: "memory")
#define CP_WAIT1()  asm volatile("cp.async.wait_group 1;" ::: "memory")

__device__ __forceinline__ void cvt_split(float4 v, uint2& hi, uint2& lo) {
    __nv_bfloat162 h0 = __floats2bfloat162_rn(v.x, v.y);
    __nv_bfloat162 h1 = __floats2bfloat162_rn(v.z, v.w);
    float rx = __bfloat162float(h0.x), ry = __bfloat162float(h0.y);
    float rz = __bfloat162float(h1.x), rw = __bfloat162float(h1.y);
    __nv_bfloat162 l0 = __floats2bfloat162_rn(v.x - rx, v.y - ry);
    __nv_bfloat162 l1 = __floats2bfloat162_rn(v.z - rz, v.w - rw);
    hi.x = *(uint32_t*)&h0; hi.y = *(uint32_t*)&h1;
    lo.x = *(uint32_t*)&l0; lo.y = *(uint32_t*)&l1;
}
__device__ __forceinline__ void split2(float x, float y, uint32_t& h, uint32_t& l) {
    __nv_bfloat162 hh = __floats2bfloat162_rn(x, y);
    h = *(uint32_t*)&hh;
    __nv_bfloat162 ll = __floats2bfloat162_rn(x - __bfloat162float(hh.x),
                                              y - __bfloat162float(hh.y));
    l = *(uint32_t*)&ll;
}

// ---------------- fp32 -> split bf16 planes ----------------
__global__ void __launch_bounds__(256)
split_f32(const float* __restrict__ in, __nv_bfloat16* __restrict__ h,
          __nv_bfloat16* __restrict__ l, int n4)
{
    int i = blockIdx.x * blockDim.x + threadIdx.x;
    if (i < n4) {
        float4 v = ((const float4*)in)[i];
        uint2 hi, lo;
        cvt_split(v, hi, lo);
        ((uint2*)h)[i] = hi;
        ((uint2*)l)[i] = lo;
    }
}

// ================= pre-split GEMM, PIPE=3, 1 CTA/SM, unrestricted regs =======
#define ROWB    80
#define PLANE_B (128 * ROWB)      // 10240
#define BUF_B   (4 * PLANE_B)     // 40960
#define PIPE    3
#define GEMM_SMEM (PIPE * BUF_B)  // 122880 -> 1 CTA/SM

__device__ __forceinline__ void mma_block(float acc[2][8][4],
        const uint32_t a[2][4], const uint32_t b[4][4]) {
    #pragma unroll
    for (int mt = 0; mt < 2; mt++)
        #pragma unroll
        for (int p = 0; p < 4; p++) {
            uint32_t b0[2] = { b[p][0], b[p][2] };
            uint32_t b1[2] = { b[p][1], b[p][3] };
            mma16816(acc[mt][2*p+0], a[mt], b0);
            mma16816(acc[mt][2*p+1], a[mt], b1);
        }
}

template<bool SPLIT_OUT>
__global__ void __launch_bounds__(256)
gemm_pre(const __nv_bfloat16* __restrict__ Ah, const __nv_bfloat16* __restrict__ Al,
         const __nv_bfloat16* __restrict__ Wh, const __nv_bfloat16* __restrict__ Wl,
         const float* __restrict__ bias,
         float* __restrict__ Cf,
         __nv_bfloat16* __restrict__ Ch, __nv_bfloat16* __restrict__ Cl,
         int M, int N, int K, int qcols, float qscale)
{
    extern __shared__ __align__(128) char smem[];
    const uint32_t sb = smem_u32(smem);
    const int tid = threadIdx.x;
    const int lane = tid & 31, wid = tid >> 5;
    const int wm = wid >> 1, wn = wid & 1;
    const int m0 = blockIdx.y * 128;
    const int n0 = blockIdx.x * 128;

    float acc[2][8][4] = {};

    const int frow = lane & 15;
    const int fcol = ((lane >> 4) & 1) * 16;
    uint32_t a_addr[2], b_addr[4];
    #pragma unroll
    for (int mt = 0; mt < 2; mt++)
        a_addr[mt] = (uint32_t)((wm * 32 + mt * 16 + frow) * ROWB + fcol);
    #pragma unroll
    for (int p = 0; p < 4; p++)
        b_addr[p] = (uint32_t)((wn * 64 + p * 16 + frow) * ROWB + fcol);

    auto issue = [&](int stage, int k0) {
        const uint32_t sbuf = sb + stage * BUF_B;
        #pragma unroll
        for (int j = 0; j < 2; j++) {
            int cid = tid + j * 256;
            int r = cid >> 2, c16 = cid & 3;
            uint32_t so = (uint32_t)(r * ROWB + c16 * 16);
            size_t ga = (size_t)(m0 + r) * K + k0 + c16 * 8;
            size_t gb = (size_t)(n0 + r) * K + k0 + c16 * 8;
            CP16(sbuf + 0 * PLANE_B + so, Ah + ga);
            CP16(sbuf + 1 * PLANE_B + so, Al + ga);
            CP16(sbuf + 2 * PLANE_B + so, Wh + gb);
            CP16(sbuf + 3 * PLANE_B + so, Wl + gb);
        }
        CP_COMMIT();
    };

    const int nch = K / 32;
    issue(0, 0);
    issue(1, 32);

    for (int i = 0; i < nch; i++) {
        CP_WAIT1();            // stage i landed (stage i+1 may still fly)
        __syncthreads();       // everyone done reading stage (i+2)%PIPE's buffer
        if (i + 2 < nch) issue((i + 2) % PIPE, (i + 2) * 32);

        const uint32_t base = sb + (i % PIPE) * BUF_B;

        uint32_t a0h[2][4], a0l[2][4], b0h[4][4], b0l[4][4];
        uint32_t a1h[2][4], a1l[2][4], b1h[4][4], b1l[4][4];

        // fragments for kh=0 (hh operands first)
        #pragma unroll
        for (int mt = 0; mt < 2; mt++) {
            ldm_x4(a0h[mt], base + 0 * PLANE_B + a_addr[mt]);
            ldm_x4(a0l[mt], base + 1 * PLANE_B + a_addr[mt]);
        }
        #pragma unroll
        for (int p = 0; p < 4; p++)
            ldm_x4(b0h[p], base + 2 * PLANE_B + b_addr[p]);

        // prefetch Bl(0) under hh(0)
        #pragma unroll
        for (int p = 0; p < 4; p++)
            ldm_x4(b0l[p], base + 3 * PLANE_B + b_addr[p]);

        mma_block(acc, a0h, b0h);      // hh(0)

        // prefetch A(1), Bh(1) under lh(0)/hl(0)
        #pragma unroll
        for (int mt = 0; mt < 2; mt++) {
            ldm_x4(a1h[mt], base + 0 * PLANE_B + a_addr[mt] + 32);
            ldm_x4(a1l[mt], base + 1 * PLANE_B + a_addr[mt] + 32);
        }
        #pragma unroll
        for (int p = 0; p < 4; p++)
            ldm_x4(b1h[p], base + 2 * PLANE_B + b_addr[p] + 32);

        mma_block(acc, a0l, b0h);      // lh(0)
        mma_block(acc, a0h, b0l);      // hl(0)

        // prefetch Bl(1) under hh(1)
        #pragma unroll
        for (int p = 0; p < 4; p++)
            ldm_x4(b1l[p], base + 3 * PLANE_B + b_addr[p] + 32);

        mma_block(acc, a1h, b1h);      // hh(1)
        mma_block(acc, a1l, b1h);      // lh(1)
        mma_block(acc, a1h, b1l);      // hl(1)
    }

    // epilogue
    const int g = lane >> 2, t = lane & 3;
    #pragma unroll
    for (int mt = 0; mt < 2; mt++) {
        int row = m0 + wm * 32 + mt * 16 + g;
        #pragma unroll
        for (int nt = 0; nt < 8; nt++) {
            int col = n0 + wn * 64 + nt * 8 + t * 2;
            float bx = bias[col], by = bias[col + 1];
            float* c = acc[mt][nt];
            float v0 = c[0] + bx, v1 = c[1] + by;
            float v2 = c[2] + bx, v3 = c[3] + by;
            if (SPLIT_OUT) {
                float s = (col < qcols) ? qscale : 1.0f;
                uint32_t h0, l0, h1, l1;
                split2(v0 * s, v1 * s, h0, l0);
                split2(v2 * s, v3 * s, h1, l1);
                *(uint32_t*)&Ch[(size_t)row * N + col] = h0;
                *(uint32_t*)&Cl[(size_t)row * N + col] = l0;
                *(uint32_t*)&Ch[(size_t)(row + 8) * N + col] = h1;
                *(uint32_t*)&Cl[(size_t)(row + 8) * N + col] = l1;
            } else {
                *(float2*)(Cf + (size_t)row * N + col) = make_float2(v0, v1);
                *(float2*)(Cf + (size_t)(row + 8) * N + col) = make_float2(v2, v3);
            }
        }
    }
}

// ================= HMMA flash attention: cp.async double-buffered KV =================
// (unchanged from round 9 — known-good)
#define KSTR 144
#define KV_PL   (64 * KSTR)                  // 9216 per plane
#define KV_B    (4 * KV_PL)                  // 36864 per stage
#define AQH 0
#define AQL (128 * KSTR)                     // 18432
#define AKV (2 * 128 * KSTR)                 // 36864
#define ATT_SMEM (AKV + 2 * KV_B)            // 110592 -> 2 CTAs/SM

__global__ void __launch_bounds__(256, 2)
attn_pre(const __nv_bfloat16* __restrict__ qkvh,
         const __nv_bfloat16* __restrict__ qkvl,
         __nv_bfloat16* __restrict__ atth,
         __nv_bfloat16* __restrict__ attl)
{
    extern __shared__ __align__(128) char smem[];
    const uint32_t sb = smem_u32(smem);
    const int tid = threadIdx.x;
    const int lane = tid & 31, wid = tid >> 5;
    const int b = blockIdx.y >> 4, h = blockIdx.y & 15;
    const int q0 = blockIdx.x * 128;

    const size_t rs = 3 * EMB;
    const __nv_bfloat16* Qh = qkvh + (size_t)(b * SEQ) * rs + h * HD;
    const __nv_bfloat16* Ql = qkvl + (size_t)(b * SEQ) * rs + h * HD;
    const __nv_bfloat16* Kh = Qh + EMB;
    const __nv_bfloat16* Kl = Ql + EMB;
    const __nv_bfloat16* Vh = Qh + 2 * EMB;
    const __nv_bfloat16* Vl = Ql + 2 * EMB;

    auto issueKV = [&](int stage, int k0) {
        const uint32_t sbuf = sb + AKV + stage * KV_B;
        #pragma unroll
        for (int i = 0; i < 2; i++) {
            int idx = tid + i * 256;           // 0..511
            int r = idx >> 3, c16 = idx & 7;
            size_t go = (size_t)(k0 + r) * rs + c16 * 8;
            uint32_t so = (uint32_t)(r * KSTR + c16 * 16);
            CP16(sbuf + 0 * KV_PL + so, Kh + go);
            CP16(sbuf + 1 * KV_PL + so, Kl + go);
            CP16(sbuf + 2 * KV_PL + so, Vh + go);
            CP16(sbuf + 3 * KV_PL + so, Vl + go);
        }
        CP_COMMIT();
    };

    issueKV(0, 0);

    // ---- load Q tile (sync; once) ----
    #pragma unroll
    for (int i = 0; i < 4; i++) {
        int idx = tid + i * 256;
        int r = idx >> 3, c16 = idx & 7;
        size_t go = (size_t)(q0 + r) * rs + c16 * 8;
        uint32_t so = r * KSTR + c16 * 16;
        *(uint4*)(smem + AQH + so) = *(const uint4*)(Qh + go);
        *(uint4*)(smem + AQL + so) = *(const uint4*)(Ql + go);
    }

    const int frow = lane & 15;
    const int fcol = ((lane >> 4) & 1) * 16;
    const uint32_t qa = sb + AQH + (uint32_t)((wid * 16 + frow) * KSTR + fcol);
    const uint32_t kvf = (uint32_t)(frow * KSTR + fcol);
    const uint32_t QLO = AQL - AQH;

    float oacc[8][4] = {};
    float m0 = -1e30f, m1 = -1e30f;
    float l0 = 0.0f, l1 = 0.0f;

    for (int kt = 0; kt < SEQ / 64; kt++) {
        CP_WAIT0();
        __syncthreads();
        if (kt + 1 < SEQ / 64) issueKV((kt + 1) & 1, (kt + 1) * 64);

        const uint32_t base = sb + AKV + (kt & 1) * KV_B;
        const uint32_t ka = base + 0 * KV_PL + kvf;
        const uint32_t kaL = base + 1 * KV_PL + kvf;
        const uint32_t va = base + 2 * KV_PL + kvf;
        const uint32_t vaL = base + 3 * KV_PL + kvf;

        // ---- S = Q @ K^T (16 x 64 per warp) ----
        float sacc[8][4] = {};
        #pragma unroll
        for (int kk = 0; kk < 4; kk++) {
            uint32_t aqh[4], aql[4], kf[4][4];
            ldm_x4(aqh, qa + kk * 32);
            ldm_x4(aql, qa + QLO + kk * 32);
            #pragma unroll
            for (int p = 0; p < 4; p++)
                ldm_x4(kf[p], ka + p * (16 * KSTR) + kk * 32);
            #pragma unroll
            for (int p = 0; p < 4; p++) {
                uint32_t b0[2] = { kf[p][0], kf[p][2] };
                uint32_t b1[2] = { kf[p][1], kf[p][3] };
                mma16816(sacc[2*p+0], aqh, b0);
                mma16816(sacc[2*p+1], aqh, b1);
            }
            #pragma unroll
            for (int p = 0; p < 4; p++) {
                uint32_t b0[2] = { kf[p][0], kf[p][2] };
                uint32_t b1[2] = { kf[p][1], kf[p][3] };
                mma16816(sacc[2*p+0], aql, b0);
                mma16816(sacc[2*p+1], aql, b1);
            }
            #pragma unroll
            for (int p = 0; p < 4; p++)
                ldm_x4(kf[p], kaL + p * (16 * KSTR) + kk * 32);
            #pragma unroll
            for (int p = 0; p < 4; p++) {
                uint32_t b0[2] = { kf[p][0], kf[p][2] };
                uint32_t b1[2] = { kf[p][1], kf[p][3] };
                mma16816(sacc[2*p+0], aqh, b0);
                mma16816(sacc[2*p+1], aqh, b1);
            }
        }

        // ---- online softmax (base-2, warp-local) ----
        float mx0 = -1e30f, mx1 = -1e30f;
        #pragma unroll
        for (int nt = 0; nt < 8; nt++) {
            mx0 = fmaxf(mx0, fmaxf(sacc[nt][0], sacc[nt][1]));
            mx1 = fmaxf(mx1, fmaxf(sacc[nt][2], sacc[nt][3]));
        }
        mx0 = fmaxf(mx0, __shfl_xor_sync(0xffffffffu, mx0, 1));
        mx0 = fmaxf(mx0, __shfl_xor_sync(0xffffffffu, mx0, 2));
        mx1 = fmaxf(mx1, __shfl_xor_sync(0xffffffffu, mx1, 1));
        mx1 = fmaxf(mx1, __shfl_xor_sync(0xffffffffu, mx1, 2));
        float mn0 = fmaxf(m0, mx0), mn1 = fmaxf(m1, mx1);
        float a0 = exp2f(m0 - mn0), a1 = exp2f(m1 - mn1);
        m0 = mn0; m1 = mn1;

        float ls0 = 0.0f, ls1 = 0.0f;
        #pragma unroll
        for (int nt = 0; nt < 8; nt++) {
            sacc[nt][0] = exp2f(sacc[nt][0] - mn0);
            sacc[nt][1] = exp2f(sacc[nt][1] - mn0);
            sacc[nt][2] = exp2f(sacc[nt][2] - mn1);
            sacc[nt][3] = exp2f(sacc[nt][3] - mn1);
            ls0 += sacc[nt][0] + sacc[nt][1];
            ls1 += sacc[nt][2] + sacc[nt][3];
        }
        l0 = l0 * a0 + ls0;
        l1 = l1 * a1 + ls1;
        #pragma unroll
        for (int nt = 0; nt < 8; nt++) {
            oacc[nt][0] *= a0; oacc[nt][1] *= a0;
            oacc[nt][2] *= a1; oacc[nt][3] *= a1;
        }

        // ---- O += P @ V (V via ldmatrix.trans; reuse V regs) ----
        #pragma unroll
        for (int kk = 0; kk < 4; kk++) {
            uint32_t ph[4], pl[4], vf[4][4];
            split2(sacc[2*kk  ][0], sacc[2*kk  ][1], ph[0], pl[0]);
            split2(sacc[2*kk  ][2], sacc[2*kk  ][3], ph[1], pl[1]);
            split2(sacc[2*kk+1][0], sacc[2*kk+1][1], ph[2], pl[2]);
            split2(sacc[2*kk+1][2], sacc[2*kk+1][3], ph[3], pl[3]);
            #pragma unroll
            for (int nd = 0; nd < 4; nd++)
                ldm_x4_t(vf[nd], va + kk * (16 * KSTR) + nd * 32);
            #pragma unroll
            for (int nd = 0; nd < 4; nd++) {
                uint32_t b0[2] = { vf[nd][0], vf[nd][1] };
                uint32_t b1[2] = { vf[nd][2], vf[nd][3] };
                mma16816(oacc[2*nd+0], ph, b0);
                mma16816(oacc[2*nd+1], ph, b1);
            }
            #pragma unroll
            for (int nd = 0; nd < 4; nd++) {
                uint32_t b0[2] = { vf[nd][0], vf[nd][1] };
                uint32_t b1[2] = { vf[nd][2], vf[nd][3] };
                mma16816(oacc[2*nd+0], pl, b0);
                mma16816(oacc[2*nd+1], pl, b1);
            }
            #pragma unroll
            for (int nd = 0; nd < 4; nd++)
                ldm_x4_t(vf[nd], vaL + kk * (16 * KSTR) + nd * 32);
            #pragma unroll
            for (int nd = 0; nd < 4; nd++) {
                uint32_t b0[2] = { vf[nd][0], vf[nd][1] };
                uint32_t b1[2] = { vf[nd][2], vf[nd][3] };
                mma16816(oacc[2*nd+0], ph, b0);
                mma16816(oacc[2*nd+1], ph, b1);
            }
        }
    }

    // ---- finalize ----
    l0 += __shfl_xor_sync(0xffffffffu, l0, 1);
    l0 += __shfl_xor_sync(0xffffffffu, l0, 2);
    l1 += __shfl_xor_sync(0xffffffffu, l1, 1);
    l1 += __shfl_xor_sync(0xffffffffu, l1, 2);
    float inv0 = 1.0f / l0, inv1 = 1.0f / l1;

    const int g = lane >> 2, t = lane & 3;
    const int row = q0 + wid * 16 + g;
    size_t o0 = (size_t)(b * SEQ + row) * EMB + h * HD;
    size_t o1 = (size_t)(b * SEQ + row + 8) * EMB + h * HD;
    #pragma unroll
    for (int nt = 0; nt < 8; nt++) {
        int col = nt * 8 + t * 2;
        uint32_t h0, lo0, h1, lo1;
        split2(oacc[nt][0] * inv0, oacc[nt][1] * inv0, h0, lo0);
        split2(oacc[nt][2] * inv1, oacc[nt][3] * inv1, h1, lo1);
        *(uint32_t*)&atth[o0 + col] = h0;
        *(uint32_t*)&attl[o0 + col] = lo0;
        *(uint32_t*)&atth[o1 + col] = h1;
        *(uint32_t*)&attl[o1 + col] = lo1;
    }
}

// ---------------------------------------------------------------------------
extern "C" void kernel_launch(void* const* d_in, const int* in_sizes, int n_in,
                              void* d_out, int out_size)
{
    const float* x      = (const float*)d_in[0];
    const float* w_qkv  = (const float*)d_in[1];
    const float* b_qkv  = (const float*)d_in[2];
    const float* w_proj = (const float*)d_in[3];
    const float* b_proj = (const float*)d_in[4];
    float* out = (float*)d_out;

    __nv_bfloat16 *xh, *xl, *wqh, *wql, *wph, *wpl, *qh, *ql, *ath, *atl;
    cudaGetSymbolAddress((void**)&xh, g_xh);
    cudaGetSymbolAddress((void**)&xl, g_xl);
    cudaGetSymbolAddress((void**)&wqh, g_wqh);
    cudaGetSymbolAddress((void**)&wql, g_wql);
    cudaGetSymbolAddress((void**)&wph, g_wph);
    cudaGetSymbolAddress((void**)&wpl, g_wpl);
    cudaGetSymbolAddress((void**)&qh, g_qkvh);
    cudaGetSymbolAddress((void**)&ql, g_qkvl);
    cudaGetSymbolAddress((void**)&ath, g_atth);
    cudaGetSymbolAddress((void**)&atl, g_attl);

    cudaFuncSetAttribute(gemm_pre<true>,  cudaFuncAttributeMaxDynamicSharedMemorySize, GEMM_SMEM);
    cudaFuncSetAttribute(gemm_pre<false>, cudaFuncAttributeMaxDynamicSharedMemorySize, GEMM_SMEM);
    cudaFuncSetAttribute(attn_pre, cudaFuncAttributeMaxDynamicSharedMemorySize, ATT_SMEM);

    // 0) pre-split operands
    {
        int n4 = TOK * EMB / 4;
        split_f32<<<(n4 + 255) / 256, 256>>>(x, xh, xl, n4);
        n4 = 3 * EMB * EMB / 4;
        split_f32<<<(n4 + 255) / 256, 256>>>(w_qkv, wqh, wql, n4);
        n4 = EMB * EMB / 4;
        split_f32<<<(n4 + 255) / 256, 256>>>(w_proj, wph, wpl, n4);
    }

    const float QSCALE = 0.125f * 1.4426950408889634f;   // 1/sqrt(64) * log2(e)

    // 1) QKV projection -> split bf16 qkv (Q columns pre-scaled)
    dim3 g1(3 * EMB / 128, TOK / 128);
    gemm_pre<true><<<g1, 256, GEMM_SMEM>>>(xh, xl, wqh, wql, b_qkv,
                                           nullptr, qh, ql,
                                           TOK, 3 * EMB, EMB, EMB, QSCALE);

    // 2) Attention -> split bf16 att
    dim3 g2(SEQ / 128, BATCH * NH);
    attn_pre<<<g2, 256, ATT_SMEM>>>(qh, ql, ath, atl);

    // 3) Output projection -> fp32 out
    dim3 g3(EMB / 128, TOK / 128);
    gemm_pre<false><<<g3, 256, GEMM_SMEM>>>(ath, atl, wph, wpl, b_proj,
                                            out, nullptr, nullptr,
                                            TOK, EMB, EMB, 0, 1.0f);
}

// round 11
// speedup vs baseline: 1.2043x; 1.2043x over previous
#include <cuda_runtime.h>
#include <cuda_bf16.h>
#include <cuda_fp16.h>
#include <cstdint>

#define BATCH 4
#define SEQ   2048
#define EMB   1024
#define NH    16
#define HD    64
#define TOK   (BATCH*SEQ)      // 8192

// ---------------- scratch (device globals; allocation-free rule) ----------
__device__ __nv_bfloat16 g_xh[(size_t)TOK * EMB];
__device__ __nv_bfloat16 g_xl[(size_t)TOK * EMB];
__device__ __nv_bfloat16 g_wqh[(size_t)3 * EMB * EMB];
__device__ __nv_bfloat16 g_wql[(size_t)3 * EMB * EMB];
__device__ __nv_bfloat16 g_wph[(size_t)EMB * EMB];
__device__ __nv_bfloat16 g_wpl[(size_t)EMB * EMB];
// qkv planes: Q,K cols are bf16 hi/lo; V cols are fp16 hi/lo (same 16-bit storage)
__device__ __nv_bfloat16 g_qkvh[(size_t)TOK * 3 * EMB];
__device__ __nv_bfloat16 g_qkvl[(size_t)TOK * 3 * EMB];
__device__ __nv_bfloat16 g_atth[(size_t)TOK * EMB];
__device__ __nv_bfloat16 g_attl[(size_t)TOK * EMB];

// ---------------- primitives ----------------
__device__ __forceinline__ uint32_t smem_u32(const void* p) {
    uint32_t a;
    asm("{ .reg .u64 t; cvta.to.shared.u64 t, %1; cvt.u32.u64 %0, t; }" : "=r"(a) : "l"(p));
    return a;
}
__device__ __forceinline__ void ldm_x4(uint32_t* r, uint32_t addr) {
    asm volatile("ldmatrix.sync.aligned.m8n8.x4.shared.b16 {%0,%1,%2,%3}, [%4];"
        : "=r"(r[0]), "=r"(r[1]), "=r"(r[2]), "=r"(r[3]) : "r"(addr));
}
__device__ __forceinline__ void ldm_x4_t(uint32_t* r, uint32_t addr) {
    asm volatile("ldmatrix.sync.aligned.m8n8.x4.trans.shared.b16 {%0,%1,%2,%3}, [%4];"
        : "=r"(r[0]), "=r"(r[1]), "=r"(r[2]), "=r"(r[3]) : "r"(addr));
}
__device__ __forceinline__ void mma16816(float* c, const uint32_t* a, const uint32_t* b) {
    asm volatile(
        "mma.sync.aligned.m16n8k16.row.col.f32.bf16.bf16.f32 "
        "{%0,%1,%2,%3}, {%4,%5,%6,%7}, {%8,%9}, {%0,%1,%2,%3};"
        : "+f"(c[0]), "+f"(c[1]), "+f"(c[2]), "+f"(c[3])
        : "r"(a[0]), "r"(a[1]), "r"(a[2]), "r"(a[3]), "r"(b[0]), "r"(b[1]));
}
__device__ __forceinline__ void mma16816h(float* c, const uint32_t* a, const uint32_t* b) {
    asm volatile(
        "mma.sync.aligned.m16n8k16.row.col.f32.f16.f16.f32 "
        "{%0,%1,%2,%3}, {%4,%5,%6,%7}, {%8,%9}, {%0,%1,%2,%3};"
        : "+f"(c[0]), "+f"(c[1]), "+f"(c[2]), "+f"(c[3])
        : "r"(a[0]), "r"(a[1]), "r"(a[2]), "r"(a[3]), "r"(b[0]), "r"(b[1]));
}
#define CP16(dst, src) \
    asm volatile("cp.async.cg.shared.global [%0], [%1], 16;" \
        :: "r"(dst), "l"(src) : "memory")
#define CP_COMMIT() asm volatile("cp.async.commit_group;" ::: "memory")
#define CP_WAIT0()  asm volatile("cp.async.wait_group 0;" ::: "memory")

__device__ __forceinline__ void cvt_split(float4 v, uint2& hi, uint2& lo) {
    __nv_bfloat162 h0 = __floats2bfloat162_rn(v.x, v.y);
    __nv_bfloat162 h1 = __floats2bfloat162_rn(v.z, v.w);
    float rx = __bfloat162float(h0.x), ry = __bfloat162float(h0.y);
    float rz = __bfloat162float(h1.x), rw = __bfloat162float(h1.y);
    __nv_bfloat162 l0 = __floats2bfloat162_rn(v.x - rx, v.y - ry);
    __nv_bfloat162 l1 = __floats2bfloat162_rn(v.z - rz, v.w - rw);
    hi.x = *(uint32_t*)&h0; hi.y = *(uint32_t*)&h1;
    lo.x = *(uint32_t*)&l0; lo.y = *(uint32_t*)&l1;
}
__device__ __forceinline__ void split2(float x, float y, uint32_t& h, uint32_t& l) {
    __nv_bfloat162 hh = __floats2bfloat162_rn(x, y);
    h = *(uint32_t*)&hh;
    __nv_bfloat162 ll = __floats2bfloat162_rn(x - __bfloat162float(hh.x),
                                              y - __bfloat162float(hh.y));
    l = *(uint32_t*)&ll;
}
// fp16 split (for V)
__device__ __forceinline__ void split2h(float x, float y, uint32_t& h, uint32_t& l) {
    __half2 hh = __floats2half2_rn(x, y);
    h = *(uint32_t*)&hh;
    float rx = __half2float(__low2half(hh)), ry = __half2float(__high2half(hh));
    __half2 ll = __floats2half2_rn(x - rx, y - ry);
    l = *(uint32_t*)&ll;
}
__device__ __forceinline__ uint32_t pack_h2(float x, float y) {
    __half2 h = __floats2half2_rn(x, y);
    return *(uint32_t*)&h;
}

// ---------------- fp32 -> split bf16 planes ----------------
__global__ void __launch_bounds__(256)
split_f32(const float* __restrict__ in, __nv_bfloat16* __restrict__ h,
          __nv_bfloat16* __restrict__ l, int n4)
{
    int i = blockIdx.x * blockDim.x + threadIdx.x;
    if (i < n4) {
        float4 v = ((const float4*)in)[i];
        uint2 hi, lo;
        cvt_split(v, hi, lo);
        ((uint2*)h)[i] = hi;
        ((uint2*)l)[i] = lo;
    }
}

// ======== pre-split GEMM (round-9 config: 2-stage, fragment-pipelined) ========
#define ROWB    80
#define PLANE_B (128 * ROWB)      // 10240
#define BUF_B   (4 * PLANE_B)     // 40960
#define GEMM_SMEM (2 * BUF_B)     // 81920 -> 2 CTAs/SM

__device__ __forceinline__ void mma_block(float acc[2][8][4],
        const uint32_t a[2][4], const uint32_t b[4][4]) {
    #pragma unroll
    for (int mt = 0; mt < 2; mt++)
        #pragma unroll
        for (int p = 0; p < 4; p++) {
            uint32_t b0[2] = { b[p][0], b[p][2] };
            uint32_t b1[2] = { b[p][1], b[p][3] };
            mma16816(acc[mt][2*p+0], a[mt], b0);
            mma16816(acc[mt][2*p+1], a[mt], b1);
        }
}

template<bool SPLIT_OUT>
__global__ void __launch_bounds__(256)
gemm_pre(const __nv_bfloat16* __restrict__ Ah, const __nv_bfloat16* __restrict__ Al,
         const __nv_bfloat16* __restrict__ Wh, const __nv_bfloat16* __restrict__ Wl,
         const float* __restrict__ bias,
         float* __restrict__ Cf,
         __nv_bfloat16* __restrict__ Ch, __nv_bfloat16* __restrict__ Cl,
         int M, int N, int K, int qcols, int vcols, float qscale)
{
    extern __shared__ __align__(128) char smem[];
    const uint32_t sb = smem_u32(smem);
    const int tid = threadIdx.x;
    const int lane = tid & 31, wid = tid >> 5;
    const int wm = wid >> 1, wn = wid & 1;
    const int m0 = blockIdx.y * 128;
    const int n0 = blockIdx.x * 128;

    float acc[2][8][4] = {};

    const int frow = lane & 15;
    const int fcol = ((lane >> 4) & 1) * 16;
    uint32_t a_addr[2], b_addr[4];
    #pragma unroll
    for (int mt = 0; mt < 2; mt++)
        a_addr[mt] = (uint32_t)((wm * 32 + mt * 16 + frow) * ROWB + fcol);
    #pragma unroll
    for (int p = 0; p < 4; p++)
        b_addr[p] = (uint32_t)((wn * 64 + p * 16 + frow) * ROWB + fcol);

    auto issue = [&](int stage, int k0) {
        const uint32_t sbuf = sb + stage * BUF_B;
        #pragma unroll
        for (int j = 0; j < 2; j++) {
            int cid = tid + j * 256;
            int r = cid >> 2, c16 = cid & 3;
            uint32_t so = (uint32_t)(r * ROWB + c16 * 16);
            size_t ga = (size_t)(m0 + r) * K + k0 + c16 * 8;
            size_t gb = (size_t)(n0 + r) * K + k0 + c16 * 8;
            CP16(sbuf + 0 * PLANE_B + so, Ah + ga);
            CP16(sbuf + 1 * PLANE_B + so, Al + ga);
            CP16(sbuf + 2 * PLANE_B + so, Wh + gb);
            CP16(sbuf + 3 * PLANE_B + so, Wl + gb);
        }
        CP_COMMIT();
    };

    const int nch = K / 32;
    issue(0, 0);

    for (int i = 0; i < nch; i++) {
        CP_WAIT0();            // stage i landed
        __syncthreads();       // everyone done with stage i-1
        const uint32_t base = sb + (i & 1) * BUF_B;

        uint32_t a0h[2][4], a0l[2][4], b0h[4][4], b0l[4][4];
        uint32_t a1h[2][4], a1l[2][4], b1h[4][4], b1l[4][4];

        // fragments for kh=0 (hh operands first)
        #pragma unroll
        for (int mt = 0; mt < 2; mt++) {
            ldm_x4(a0h[mt], base + 0 * PLANE_B + a_addr[mt]);
            ldm_x4(a0l[mt], base + 1 * PLANE_B + a_addr[mt]);
        }
        #pragma unroll
        for (int p = 0; p < 4; p++)
            ldm_x4(b0h[p], base + 2 * PLANE_B + b_addr[p]);

        if (i + 1 < nch) issue((i + 1) & 1, (i + 1) * 32);

        // prefetch Bl(0) under hh(0)
        #pragma unroll
        for (int p = 0; p < 4; p++)
            ldm_x4(b0l[p], base + 3 * PLANE_B + b_addr[p]);

        mma_block(acc, a0h, b0h);      // hh(0)

        // prefetch A(1), Bh(1) under lh(0)/hl(0)
        #pragma unroll
        for (int mt = 0; mt < 2; mt++) {
            ldm_x4(a1h[mt], base + 0 * PLANE_B + a_addr[mt] + 32);
            ldm_x4(a1l[mt], base + 1 * PLANE_B + a_addr[mt] + 32);
        }
        #pragma unroll
        for (int p = 0; p < 4; p++)
            ldm_x4(b1h[p], base + 2 * PLANE_B + b_addr[p] + 32);

        mma_block(acc, a0l, b0h);      // lh(0)
        mma_block(acc, a0h, b0l);      // hl(0)

        // prefetch Bl(1) under hh(1)
        #pragma unroll
        for (int p = 0; p < 4; p++)
            ldm_x4(b1l[p], base + 3 * PLANE_B + b_addr[p] + 32);

        mma_block(acc, a1h, b1h);      // hh(1)
        mma_block(acc, a1l, b1h);      // lh(1)
        mma_block(acc, a1h, b1l);      // hl(1)
    }

    // epilogue
    const int g = lane >> 2, t = lane & 3;
    #pragma unroll
    for (int mt = 0; mt < 2; mt++) {
        int row = m0 + wm * 32 + mt * 16 + g;
        #pragma unroll
        for (int nt = 0; nt < 8; nt++) {
            int col = n0 + wn * 64 + nt * 8 + t * 2;
            float bx = bias[col], by = bias[col + 1];
            float* c = acc[mt][nt];
            float v0 = c[0] + bx, v1 = c[1] + by;
            float v2 = c[2] + bx, v3 = c[3] + by;
            if (SPLIT_OUT) {
                uint32_t h0, l0, h1, l1;
                if (col >= vcols) {
                    // V columns: fp16 split (consumed by fp16 PV mma)
                    split2h(v0, v1, h0, l0);
                    split2h(v2, v3, h1, l1);
                } else {
                    float s = (col < qcols) ? qscale : 1.0f;
                    split2(v0 * s, v1 * s, h0, l0);
                    split2(v2 * s, v3 * s, h1, l1);
                }
                *(uint32_t*)&Ch[(size_t)row * N + col] = h0;
                *(uint32_t*)&Cl[(size_t)row * N + col] = l0;
                *(uint32_t*)&Ch[(size_t)(row + 8) * N + col] = h1;
                *(uint32_t*)&Cl[(size_t)(row + 8) * N + col] = l1;
            } else {
                *(float2*)(Cf + (size_t)row * N + col) = make_float2(v0, v1);
                *(float2*)(Cf + (size_t)(row + 8) * N + col) = make_float2(v2, v3);
            }
        }
    }
}

// ================= HMMA flash attention: fp16 P/V in PV =================
#define KSTR 144
#define KV_PL   (64 * KSTR)                  // 9216 per plane
#define KV_B    (4 * KV_PL)                  // 36864 per stage
#define AQH 0
#define AQL (128 * KSTR)                     // 18432
#define AKV (2 * 128 * KSTR)                 // 36864
#define ATT_SMEM (AKV + 2 * KV_B)            // 110592 -> 2 CTAs/SM

__global__ void __launch_bounds__(256, 2)
attn_pre(const __nv_bfloat16* __restrict__ qkvh,
         const __nv_bfloat16* __restrict__ qkvl,
         __nv_bfloat16* __restrict__ atth,
         __nv_bfloat16* __restrict__ attl)
{
    extern __shared__ __align__(128) char smem[];
    const uint32_t sb = smem_u32(smem);
    const int tid = threadIdx.x;
    const int lane = tid & 31, wid = tid >> 5;
    const int b = blockIdx.y >> 4, h = blockIdx.y & 15;
    const int q0 = blockIdx.x * 128;

    const size_t rs = 3 * EMB;
    const __nv_bfloat16* Qh = qkvh + (size_t)(b * SEQ) * rs + h * HD;
    const __nv_bfloat16* Ql = qkvl + (size_t)(b * SEQ) * rs + h * HD;
    const __nv_bfloat16* Kh = Qh + EMB;
    const __nv_bfloat16* Kl = Ql + EMB;
    const __nv_bfloat16* Vh = Qh + 2 * EMB;   // fp16 bits
    const __nv_bfloat16* Vl = Ql + 2 * EMB;   // fp16 bits

    auto issueKV = [&](int stage, int k0) {
        const uint32_t sbuf = sb + AKV + stage * KV_B;
        #pragma unroll
        for (int i = 0; i < 2; i++) {
            int idx = tid + i * 256;           // 0..511
            int r = idx >> 3, c16 = idx & 7;
            size_t go = (size_t)(k0 + r) * rs + c16 * 8;
            uint32_t so = (uint32_t)(r * KSTR + c16 * 16);
            CP16(sbuf + 0 * KV_PL + so, Kh + go);
            CP16(sbuf + 1 * KV_PL + so, Kl + go);
            CP16(sbuf + 2 * KV_PL + so, Vh + go);
            CP16(sbuf + 3 * KV_PL + so, Vl + go);
        }
        CP_COMMIT();
    };

    issueKV(0, 0);

    // ---- load Q tile (sync; once) ----
    #pragma unroll
    for (int i = 0; i < 4; i++) {
        int idx = tid + i * 256;
        int r = idx >> 3, c16 = idx & 7;
        size_t go = (size_t)(q0 + r) * rs + c16 * 8;
        uint32_t so = r * KSTR + c16 * 16;
        *(uint4*)(smem + AQH + so) = *(const uint4*)(Qh + go);
        *(uint4*)(smem + AQL + so) = *(const uint4*)(Ql + go);
    }

    const int frow = lane & 15;
    const int fcol = ((lane >> 4) & 1) * 16;
    const uint32_t qa = sb + AQH + (uint32_t)((wid * 16 + frow) * KSTR + fcol);
    const uint32_t kvf = (uint32_t)(frow * KSTR + fcol);
    const uint32_t QLO = AQL - AQH;

    float oacc[8][4] = {};
    float m0 = -1e30f, m1 = -1e30f;
    float l0 = 0.0f, l1 = 0.0f;

    for (int kt = 0; kt < SEQ / 64; kt++) {
        CP_WAIT0();
        __syncthreads();
        if (kt + 1 < SEQ / 64) issueKV((kt + 1) & 1, (kt + 1) * 64);

        const uint32_t base = sb + AKV + (kt & 1) * KV_B;
        const uint32_t ka = base + 0 * KV_PL + kvf;
        const uint32_t kaL = base + 1 * KV_PL + kvf;
        const uint32_t va = base + 2 * KV_PL + kvf;
        const uint32_t vaL = base + 3 * KV_PL + kvf;

        // ---- S = Q @ K^T (16 x 64 per warp, bf16x3) ----
        float sacc[8][4] = {};
        #pragma unroll
        for (int kk = 0; kk < 4; kk++) {
            uint32_t aqh[4], aql[4], kf[4][4];
            ldm_x4(aqh, qa + kk * 32);
            ldm_x4(aql, qa + QLO + kk * 32);
            #pragma unroll
            for (int p = 0; p < 4; p++)
                ldm_x4(kf[p], ka + p * (16 * KSTR) + kk * 32);
            #pragma unroll
            for (int p = 0; p < 4; p++) {
                uint32_t b0[2] = { kf[p][0], kf[p][2] };
                uint32_t b1[2] = { kf[p][1], kf[p][3] };
                mma16816(sacc[2*p+0], aqh, b0);
                mma16816(sacc[2*p+1], aqh, b1);
            }
            #pragma unroll
            for (int p = 0; p < 4; p++) {
                uint32_t b0[2] = { kf[p][0], kf[p][2] };
                uint32_t b1[2] = { kf[p][1], kf[p][3] };
                mma16816(sacc[2*p+0], aql, b0);
                mma16816(sacc[2*p+1], aql, b1);
            }
            #pragma unroll
            for (int p = 0; p < 4; p++)
                ldm_x4(kf[p], kaL + p * (16 * KSTR) + kk * 32);
            #pragma unroll
            for (int p = 0; p < 4; p++) {
                uint32_t b0[2] = { kf[p][0], kf[p][2] };
                uint32_t b1[2] = { kf[p][1], kf[p][3] };
                mma16816(sacc[2*p+0], aqh, b0);
                mma16816(sacc[2*p+1], aqh, b1);
            }
        }

        // ---- online softmax (base-2, warp-local) ----
        float mx0 = -1e30f, mx1 = -1e30f;
        #pragma unroll
        for (int nt = 0; nt < 8; nt++) {
            mx0 = fmaxf(mx0, fmaxf(sacc[nt][0], sacc[nt][1]));
            mx1 = fmaxf(mx1, fmaxf(sacc[nt][2], sacc[nt][3]));
        }
        mx0 = fmaxf(mx0, __shfl_xor_sync(0xffffffffu, mx0, 1));
        mx0 = fmaxf(mx0, __shfl_xor_sync(0xffffffffu, mx0, 2));
        mx1 = fmaxf(mx1, __shfl_xor_sync(0xffffffffu, mx1, 1));
        mx1 = fmaxf(mx1, __shfl_xor_sync(0xffffffffu, mx1, 2));
        float mn0 = fmaxf(m0, mx0), mn1 = fmaxf(m1, mx1);
        float a0 = exp2f(m0 - mn0), a1 = exp2f(m1 - mn1);
        m0 = mn0; m1 = mn1;

        float ls0 = 0.0f, ls1 = 0.0f;
        #pragma unroll
        for (int nt = 0; nt < 8; nt++) {
            sacc[nt][0] = exp2f(sacc[nt][0] - mn0);
            sacc[nt][1] = exp2f(sacc[nt][1] - mn0);
            sacc[nt][2] = exp2f(sacc[nt][2] - mn1);
            sacc[nt][3] = exp2f(sacc[nt][3] - mn1);
            ls0 += sacc[nt][0] + sacc[nt][1];
            ls1 += sacc[nt][2] + sacc[nt][3];
        }
        l0 = l0 * a0 + ls0;
        l1 = l1 * a1 + ls1;
        #pragma unroll
        for (int nt = 0; nt < 8; nt++) {
            oacc[nt][0] *= a0; oacc[nt][1] *= a0;
            oacc[nt][2] *= a1; oacc[nt][3] *= a1;
        }

        // ---- O += P @ V : P as single fp16 (2 terms), V fp16 hi/lo ----
        #pragma unroll
        for (int kk = 0; kk < 4; kk++) {
            uint32_t ph[4], vf[4][4];
            ph[0] = pack_h2(sacc[2*kk  ][0], sacc[2*kk  ][1]);
            ph[1] = pack_h2(sacc[2*kk  ][2], sacc[2*kk  ][3]);
            ph[2] = pack_h2(sacc[2*kk+1][0], sacc[2*kk+1][1]);
            ph[3] = pack_h2(sacc[2*kk+1][2], sacc[2*kk+1][3]);
            // V_hi
            #pragma unroll
            for (int nd = 0; nd < 4; nd++)
                ldm_x4_t(vf[nd], va + kk * (16 * KSTR) + nd * 32);
            #pragma unroll
            for (int nd = 0; nd < 4; nd++) {
                uint32_t b0[2] = { vf[nd][0], vf[nd][1] };
                uint32_t b1[2] = { vf[nd][2], vf[nd][3] };
                mma16816h(oacc[2*nd+0], ph, b0);
                mma16816h(oacc[2*nd+1], ph, b1);
            }
            // V_lo
            #pragma unroll
            for (int nd = 0; nd < 4; nd++)
                ldm_x4_t(vf[nd], vaL + kk * (16 * KSTR) + nd * 32);
            #pragma unroll
            for (int nd = 0; nd < 4; nd++) {
                uint32_t b0[2] = { vf[nd][0], vf[nd][1] };
                uint32_t b1[2] = { vf[nd][2], vf[nd][3] };
                mma16816h(oacc[2*nd+0], ph, b0);
                mma16816h(oacc[2*nd+1], ph, b1);
            }
        }
    }

    // ---- finalize ----
    l0 += __shfl_xor_sync(0xffffffffu, l0, 1);
    l0 += __shfl_xor_sync(0xffffffffu, l0, 2);
    l1 += __shfl_xor_sync(0xffffffffu, l1, 1);
    l1 += __shfl_xor_sync(0xffffffffu, l1, 2);
    float inv0 = 1.0f / l0, inv1 = 1.0f / l1;

    const int g = lane >> 2, t = lane & 3;
    const int row = q0 + wid * 16 + g;
    size_t o0 = (size_t)(b * SEQ + row) * EMB + h * HD;
    size_t o1 = (size_t)(b * SEQ + row + 8) * EMB + h * HD;
    #pragma unroll
    for (int nt = 0; nt < 8; nt++) {
        int col = nt * 8 + t * 2;
        uint32_t h0, lo0, h1, lo1;
        split2(oacc[nt][0] * inv0, oacc[nt][1] * inv0, h0, lo0);
        split2(oacc[nt][2] * inv1, oacc[nt][3] * inv1, h1, lo1);
        *(uint32_t*)&atth[o0 + col] = h0;
        *(uint32_t*)&attl[o0 + col] = lo0;
        *(uint32_t*)&atth[o1 + col] = h1;
        *(uint32_t*)&attl[o1 + col] = lo1;
    }
}

// ---------------------------------------------------------------------------
extern "C" void kernel_launch(void* const* d_in, const int* in_sizes, int n_in,
                              void* d_out, int out_size)
{
    const float* x      = (const float*)d_in[0];
    const float* w_qkv  = (const float*)d_in[1];
    const float* b_qkv  = (const float*)d_in[2];
    const float* w_proj = (const float*)d_in[3];
    const float* b_proj = (const float*)d_in[4];
    float* out = (float*)d_out;

    __nv_bfloat16 *xh, *xl, *wqh, *wql, *wph, *wpl, *qh, *ql, *ath, *atl;
    cudaGetSymbolAddress((void**)&xh, g_xh);
    cudaGetSymbolAddress((void**)&xl, g_xl);
    cudaGetSymbolAddress((void**)&wqh, g_wqh);
    cudaGetSymbolAddress((void**)&wql, g_wql);
    cudaGetSymbolAddress((void**)&wph, g_wph);
    cudaGetSymbolAddress((void**)&wpl, g_wpl);
    cudaGetSymbolAddress((void**)&qh, g_qkvh);
    cudaGetSymbolAddress((void**)&ql, g_qkvl);
    cudaGetSymbolAddress((void**)&ath, g_atth);
    cudaGetSymbolAddress((void**)&atl, g_attl);

    cudaFuncSetAttribute(gemm_pre<true>,  cudaFuncAttributeMaxDynamicSharedMemorySize, GEMM_SMEM);
    cudaFuncSetAttribute(gemm_pre<false>, cudaFuncAttributeMaxDynamicSharedMemorySize, GEMM_SMEM);
    cudaFuncSetAttribute(attn_pre, cudaFuncAttributeMaxDynamicSharedMemorySize, ATT_SMEM);

    // 0) pre-split operands
    {
        int n4 = TOK * EMB / 4;
        split_f32<<<(n4 + 255) / 256, 256>>>(x, xh, xl, n4);
        n4 = 3 * EMB * EMB / 4;
        split_f32<<<(n4 + 255) / 256, 256>>>(w_qkv, wqh, wql, n4);
        n4 = EMB * EMB / 4;
        split_f32<<<(n4 + 255) / 256, 256>>>(w_proj, wph, wpl, n4);
    }

    const float QSCALE = 0.125f * 1.4426950408889634f;   // 1/sqrt(64) * log2(e)

    // 1) QKV projection -> split qkv (Q scaled bf16, K bf16, V fp16)
    dim3 g1(3 * EMB / 128, TOK / 128);
    gemm_pre<true><<<g1, 256, GEMM_SMEM>>>(xh, xl, wqh, wql, b_qkv,
                                           nullptr, qh, ql,
                                           TOK, 3 * EMB, EMB, EMB, 2 * EMB, QSCALE);

    // 2) Attention -> split bf16 att
    dim3 g2(SEQ / 128, BATCH * NH);
    attn_pre<<<g2, 256, ATT_SMEM>>>(qh, ql, ath, atl);

    // 3) Output projection -> fp32 out
    dim3 g3(EMB / 128, TOK / 128);
    gemm_pre<false><<<g3, 256, GEMM_SMEM>>>(ath, atl, wph, wpl, b_proj,
                                            out, nullptr, nullptr,
                                            TOK, EMB, EMB, 0, 1 << 30, 1.0f);
}

// round 12
// speedup vs baseline: 1.4457x; 1.2004x over previous
#include <cuda_runtime.h>
#include <cuda_bf16.h>
#include <cuda_fp16.h>
#include <cstdint>

#define BATCH 4
#define SEQ   2048
#define EMB   1024
#define NH    16
#define HD    64
#define TOK   (BATCH*SEQ)      // 8192

// ---------------- scratch (device globals; 16-bit payloads) ----------
__device__ __nv_bfloat16 g_xh[(size_t)TOK * EMB];        // fp16 hi
__device__ __nv_bfloat16 g_xl[(size_t)TOK * EMB];        // fp16 lo
__device__ __nv_bfloat16 g_wq[(size_t)3 * EMB * EMB];    // fp16 (single)
__device__ __nv_bfloat16 g_wp[(size_t)EMB * EMB];        // fp16 (single)
// qkv planes: Q,K cols bf16 hi/lo; V cols fp16 hi/lo
__device__ __nv_bfloat16 g_qkvh[(size_t)TOK * 3 * EMB];
__device__ __nv_bfloat16 g_qkvl[(size_t)TOK * 3 * EMB];
__device__ __nv_bfloat16 g_atth[(size_t)TOK * EMB];      // fp16 hi
__device__ __nv_bfloat16 g_attl[(size_t)TOK * EMB];      // fp16 lo

// ---------------- primitives ----------------
__device__ __forceinline__ uint32_t smem_u32(const void* p) {
    uint32_t a;
    asm("{ .reg .u64 t; cvta.to.shared.u64 t, %1; cvt.u32.u64 %0, t; }" : "=r"(a) : "l"(p));
    return a;
}
__device__ __forceinline__ void ldm_x4(uint32_t* r, uint32_t addr) {
    asm volatile("ldmatrix.sync.aligned.m8n8.x4.shared.b16 {%0,%1,%2,%3}, [%4];"
        : "=r"(r[0]), "=r"(r[1]), "=r"(r[2]), "=r"(r[3]) : "r"(addr));
}
__device__ __forceinline__ void ldm_x4_t(uint32_t* r, uint32_t addr) {
    asm volatile("ldmatrix.sync.aligned.m8n8.x4.trans.shared.b16 {%0,%1,%2,%3}, [%4];"
        : "=r"(r[0]), "=r"(r[1]), "=r"(r[2]), "=r"(r[3]) : "r"(addr));
}
__device__ __forceinline__ void mma16816(float* c, const uint32_t* a, const uint32_t* b) {
    asm volatile(
        "mma.sync.aligned.m16n8k16.row.col.f32.bf16.bf16.f32 "
        "{%0,%1,%2,%3}, {%4,%5,%6,%7}, {%8,%9}, {%0,%1,%2,%3};"
        : "+f"(c[0]), "+f"(c[1]), "+f"(c[2]), "+f"(c[3])
        : "r"(a[0]), "r"(a[1]), "r"(a[2]), "r"(a[3]), "r"(b[0]), "r"(b[1]));
}
__device__ __forceinline__ void mma16816h(float* c, const uint32_t* a, const uint32_t* b) {
    asm volatile(
        "mma.sync.aligned.m16n8k16.row.col.f32.f16.f16.f32 "
        "{%0,%1,%2,%3}, {%4,%5,%6,%7}, {%8,%9}, {%0,%1,%2,%3};"
        : "+f"(c[0]), "+f"(c[1]), "+f"(c[2]), "+f"(c[3])
        : "r"(a[0]), "r"(a[1]), "r"(a[2]), "r"(a[3]), "r"(b[0]), "r"(b[1]));
}
#define CP16(dst, src) \
    asm volatile("cp.async.cg.shared.global [%0], [%1], 16;" \
        :: "r"(dst), "l"(src) : "memory")
#define CP_COMMIT() asm volatile("cp.async.commit_group;" ::: "memory")
#define CP_WAIT0()  asm volatile("cp.async.wait_group 0;" ::: "memory")

// bf16 split (Q/K epilogue + attention S path)
__device__ __forceinline__ void split2(float x, float y, uint32_t& h, uint32_t& l) {
    __nv_bfloat162 hh = __floats2bfloat162_rn(x, y);
    h = *(uint32_t*)&hh;
    __nv_bfloat162 ll = __floats2bfloat162_rn(x - __bfloat162float(hh.x),
                                              y - __bfloat162float(hh.y));
    l = *(uint32_t*)&ll;
}
// fp16 split
__device__ __forceinline__ void split2h(float x, float y, uint32_t& h, uint32_t& l) {
    __half2 hh = __floats2half2_rn(x, y);
    h = *(uint32_t*)&hh;
    float rx = __half2float(__low2half(hh)), ry = __half2float(__high2half(hh));
    __half2 ll = __floats2half2_rn(x - rx, y - ry);
    l = *(uint32_t*)&ll;
}
__device__ __forceinline__ uint32_t pack_h2(float x, float y) {
    __half2 h = __floats2half2_rn(x, y);
    return *(uint32_t*)&h;
}
__device__ __forceinline__ void cvt_splith(float4 v, uint2& hi, uint2& lo) {
    uint32_t h0, l0, h1, l1;
    split2h(v.x, v.y, h0, l0);
    split2h(v.z, v.w, h1, l1);
    hi.x = h0; hi.y = h1;
    lo.x = l0; lo.y = l1;
}

// ---------------- conversion kernels ----------------
__global__ void __launch_bounds__(256)
split_f32h(const float* __restrict__ in, __nv_bfloat16* __restrict__ h,
           __nv_bfloat16* __restrict__ l, int n4)
{
    int i = blockIdx.x * blockDim.x + threadIdx.x;
    if (i < n4) {
        float4 v = ((const float4*)in)[i];
        uint2 hi, lo;
        cvt_splith(v, hi, lo);
        ((uint2*)h)[i] = hi;
        ((uint2*)l)[i] = lo;
    }
}
__global__ void __launch_bounds__(256)
cvt_f32h(const float* __restrict__ in, __nv_bfloat16* __restrict__ h, int n4)
{
    int i = blockIdx.x * blockDim.x + threadIdx.x;
    if (i < n4) {
        float4 v = ((const float4*)in)[i];
        uint2 hi;
        hi.x = pack_h2(v.x, v.y);
        hi.y = pack_h2(v.z, v.w);
        ((uint2*)h)[i] = hi;
    }
}

// ======== fp16 2-term GEMM: C = (Ah+Al) x W16^T + bias ========
#define ROWB    80
#define PLANE_B (128 * ROWB)      // 10240
#define P_AH    0
#define P_AL    (1 * PLANE_B)
#define P_W     (2 * PLANE_B)
#define BUF_B   (3 * PLANE_B)     // 30720
#define GEMM_SMEM (2 * BUF_B)     // 61440 -> 2 CTAs/SM

__device__ __forceinline__ void mma_block_h(float acc[2][8][4],
        const uint32_t a[2][4], const uint32_t b[4][4]) {
    #pragma unroll
    for (int mt = 0; mt < 2; mt++)
        #pragma unroll
        for (int p = 0; p < 4; p++) {
            uint32_t b0[2] = { b[p][0], b[p][2] };
            uint32_t b1[2] = { b[p][1], b[p][3] };
            mma16816h(acc[mt][2*p+0], a[mt], b0);
            mma16816h(acc[mt][2*p+1], a[mt], b1);
        }
}

template<bool SPLIT_OUT>
__global__ void __launch_bounds__(256)
gemm_pre(const __nv_bfloat16* __restrict__ Ah, const __nv_bfloat16* __restrict__ Al,
         const __nv_bfloat16* __restrict__ W,
         const float* __restrict__ bias,
         float* __restrict__ Cf,
         __nv_bfloat16* __restrict__ Ch, __nv_bfloat16* __restrict__ Cl,
         int M, int N, int K, int qcols, int vcols, float qscale)
{
    extern __shared__ __align__(128) char smem[];
    const uint32_t sb = smem_u32(smem);
    const int tid = threadIdx.x;
    const int lane = tid & 31, wid = tid >> 5;
    const int wm = wid >> 1, wn = wid & 1;
    const int m0 = blockIdx.y * 128;
    const int n0 = blockIdx.x * 128;

    float acc[2][8][4] = {};

    const int frow = lane & 15;
    const int fcol = ((lane >> 4) & 1) * 16;
    uint32_t a_addr[2], b_addr[4];
    #pragma unroll
    for (int mt = 0; mt < 2; mt++)
        a_addr[mt] = (uint32_t)((wm * 32 + mt * 16 + frow) * ROWB + fcol);
    #pragma unroll
    for (int p = 0; p < 4; p++)
        b_addr[p] = (uint32_t)((wn * 64 + p * 16 + frow) * ROWB + fcol);

    auto issue = [&](int stage, int k0) {
        const uint32_t sbuf = sb + stage * BUF_B;
        #pragma unroll
        for (int j = 0; j < 2; j++) {
            int cid = tid + j * 256;
            int r = cid >> 2, c16 = cid & 3;
            uint32_t so = (uint32_t)(r * ROWB + c16 * 16);
            size_t ga = (size_t)(m0 + r) * K + k0 + c16 * 8;
            size_t gb = (size_t)(n0 + r) * K + k0 + c16 * 8;
            CP16(sbuf + P_AH + so, Ah + ga);
            CP16(sbuf + P_AL + so, Al + ga);
            CP16(sbuf + P_W  + so, W  + gb);
        }
        CP_COMMIT();
    };

    const int nch = K / 32;
    issue(0, 0);

    for (int i = 0; i < nch; i++) {
        CP_WAIT0();            // stage i landed
        __syncthreads();       // everyone done with stage i-1
        const uint32_t base = sb + (i & 1) * BUF_B;

        uint32_t a0h[2][4], a0l[2][4], b0[4][4];
        uint32_t a1h[2][4], a1l[2][4], b1[4][4];

        // fragments for kh=0
        #pragma unroll
        for (int mt = 0; mt < 2; mt++) {
            ldm_x4(a0h[mt], base + P_AH + a_addr[mt]);
            ldm_x4(a0l[mt], base + P_AL + a_addr[mt]);
        }
        #pragma unroll
        for (int p = 0; p < 4; p++)
            ldm_x4(b0[p], base + P_W + b_addr[p]);

        if (i + 1 < nch) issue((i + 1) & 1, (i + 1) * 32);

        mma_block_h(acc, a0h, b0);     // hh(0)

        // prefetch kh=1 fragments under lh(0)
        #pragma unroll
        for (int mt = 0; mt < 2; mt++) {
            ldm_x4(a1h[mt], base + P_AH + a_addr[mt] + 32);
            ldm_x4(a1l[mt], base + P_AL + a_addr[mt] + 32);
        }
        #pragma unroll
        for (int p = 0; p < 4; p++)
            ldm_x4(b1[p], base + P_W + b_addr[p] + 32);

        mma_block_h(acc, a0l, b0);     // lh(0)
        mma_block_h(acc, a1h, b1);     // hh(1)
        mma_block_h(acc, a1l, b1);     // lh(1)
    }

    // epilogue
    const int g = lane >> 2, t = lane & 3;
    #pragma unroll
    for (int mt = 0; mt < 2; mt++) {
        int row = m0 + wm * 32 + mt * 16 + g;
        #pragma unroll
        for (int nt = 0; nt < 8; nt++) {
            int col = n0 + wn * 64 + nt * 8 + t * 2;
            float bx = bias[col], by = bias[col + 1];
            float* c = acc[mt][nt];
            float v0 = c[0] + bx, v1 = c[1] + by;
            float v2 = c[2] + bx, v3 = c[3] + by;
            if (SPLIT_OUT) {
                uint32_t h0, l0, h1, l1;
                if (col >= vcols) {
                    split2h(v0, v1, h0, l0);   // V: fp16 split
                    split2h(v2, v3, h1, l1);
                } else {
                    float s = (col < qcols) ? qscale : 1.0f;
                    split2(v0 * s, v1 * s, h0, l0);   // Q/K: bf16 split
                    split2(v2 * s, v3 * s, h1, l1);
                }
                *(uint32_t*)&Ch[(size_t)row * N + col] = h0;
                *(uint32_t*)&Cl[(size_t)row * N + col] = l0;
                *(uint32_t*)&Ch[(size_t)(row + 8) * N + col] = h1;
                *(uint32_t*)&Cl[(size_t)(row + 8) * N + col] = l1;
            } else {
                *(float2*)(Cf + (size_t)row * N + col) = make_float2(v0, v1);
                *(float2*)(Cf + (size_t)(row + 8) * N + col) = make_float2(v2, v3);
            }
        }
    }
}

// ================= HMMA flash attention (round-11 config; fp16 out) ==========
#define KSTR 144
#define KV_PL   (64 * KSTR)                  // 9216 per plane
#define KV_B    (4 * KV_PL)                  // 36864 per stage
#define AQH 0
#define AQL (128 * KSTR)                     // 18432
#define AKV (2 * 128 * KSTR)                 // 36864
#define ATT_SMEM (AKV + 2 * KV_B)            // 110592 -> 2 CTAs/SM

__global__ void __launch_bounds__(256, 2)
attn_pre(const __nv_bfloat16* __restrict__ qkvh,
         const __nv_bfloat16* __restrict__ qkvl,
         __nv_bfloat16* __restrict__ atth,
         __nv_bfloat16* __restrict__ attl)
{
    extern __shared__ __align__(128) char smem[];
    const uint32_t sb = smem_u32(smem);
    const int tid = threadIdx.x;
    const int lane = tid & 31, wid = tid >> 5;
    const int b = blockIdx.y >> 4, h = blockIdx.y & 15;
    const int q0 = blockIdx.x * 128;

    const size_t rs = 3 * EMB;
    const __nv_bfloat16* Qh = qkvh + (size_t)(b * SEQ) * rs + h * HD;
    const __nv_bfloat16* Ql = qkvl + (size_t)(b * SEQ) * rs + h * HD;
    const __nv_bfloat16* Kh = Qh + EMB;
    const __nv_bfloat16* Kl = Ql + EMB;
    const __nv_bfloat16* Vh = Qh + 2 * EMB;   // fp16 bits
    const __nv_bfloat16* Vl = Ql + 2 * EMB;   // fp16 bits

    auto issueKV = [&](int stage, int k0) {
        const uint32_t sbuf = sb + AKV + stage * KV_B;
        #pragma unroll
        for (int i = 0; i < 2; i++) {
            int idx = tid + i * 256;           // 0..511
            int r = idx >> 3, c16 = idx & 7;
            size_t go = (size_t)(k0 + r) * rs + c16 * 8;
            uint32_t so = (uint32_t)(r * KSTR + c16 * 16);
            CP16(sbuf + 0 * KV_PL + so, Kh + go);
            CP16(sbuf + 1 * KV_PL + so, Kl + go);
            CP16(sbuf + 2 * KV_PL + so, Vh + go);
            CP16(sbuf + 3 * KV_PL + so, Vl + go);
        }
        CP_COMMIT();
    };

    issueKV(0, 0);

    // ---- load Q tile (sync; once) ----
    #pragma unroll
    for (int i = 0; i < 4; i++) {
        int idx = tid + i * 256;
        int r = idx >> 3, c16 = idx & 7;
        size_t go = (size_t)(q0 + r) * rs + c16 * 8;
        uint32_t so = r * KSTR + c16 * 16;
        *(uint4*)(smem + AQH + so) = *(const uint4*)(Qh + go);
        *(uint4*)(smem + AQL + so) = *(const uint4*)(Ql + go);
    }

    const int frow = lane & 15;
    const int fcol = ((lane >> 4) & 1) * 16;
    const uint32_t qa = sb + AQH + (uint32_t)((wid * 16 + frow) * KSTR + fcol);
    const uint32_t kvf = (uint32_t)(frow * KSTR + fcol);
    const uint32_t QLO = AQL - AQH;

    float oacc[8][4] = {};
    float m0 = -1e30f, m1 = -1e30f;
    float l0 = 0.0f, l1 = 0.0f;

    for (int kt = 0; kt < SEQ / 64; kt++) {
        CP_WAIT0();
        __syncthreads();
        if (kt + 1 < SEQ / 64) issueKV((kt + 1) & 1, (kt + 1) * 64);

        const uint32_t base = sb + AKV + (kt & 1) * KV_B;
        const uint32_t ka = base + 0 * KV_PL + kvf;
        const uint32_t kaL = base + 1 * KV_PL + kvf;
        const uint32_t va = base + 2 * KV_PL + kvf;
        const uint32_t vaL = base + 3 * KV_PL + kvf;

        // ---- S = Q @ K^T (16 x 64 per warp, bf16x3) ----
        float sacc[8][4] = {};
        #pragma unroll
        for (int kk = 0; kk < 4; kk++) {
            uint32_t aqh[4], aql[4], kf[4][4];
            ldm_x4(aqh, qa + kk * 32);
            ldm_x4(aql, qa + QLO + kk * 32);
            #pragma unroll
            for (int p = 0; p < 4; p++)
                ldm_x4(kf[p], ka + p * (16 * KSTR) + kk * 32);
            #pragma unroll
            for (int p = 0; p < 4; p++) {
                uint32_t b0[2] = { kf[p][0], kf[p][2] };
                uint32_t b1[2] = { kf[p][1], kf[p][3] };
                mma16816(sacc[2*p+0], aqh, b0);
                mma16816(sacc[2*p+1], aqh, b1);
            }
            #pragma unroll
            for (int p = 0; p < 4; p++) {
                uint32_t b0[2] = { kf[p][0], kf[p][2] };
                uint32_t b1[2] = { kf[p][1], kf[p][3] };
                mma16816(sacc[2*p+0], aql, b0);
                mma16816(sacc[2*p+1], aql, b1);
            }
            #pragma unroll
            for (int p = 0; p < 4; p++)
                ldm_x4(kf[p], kaL + p * (16 * KSTR) + kk * 32);
            #pragma unroll
            for (int p = 0; p < 4; p++) {
                uint32_t b0[2] = { kf[p][0], kf[p][2] };
                uint32_t b1[2] = { kf[p][1], kf[p][3] };
                mma16816(sacc[2*p+0], aqh, b0);
                mma16816(sacc[2*p+1], aqh, b1);
            }
        }

        // ---- online softmax (base-2, warp-local) ----
        float mx0 = -1e30f, mx1 = -1e30f;
        #pragma unroll
        for (int nt = 0; nt < 8; nt++) {
            mx0 = fmaxf(mx0, fmaxf(sacc[nt][0], sacc[nt][1]));
            mx1 = fmaxf(mx1, fmaxf(sacc[nt][2], sacc[nt][3]));
        }
        mx0 = fmaxf(mx0, __shfl_xor_sync(0xffffffffu, mx0, 1));
        mx0 = fmaxf(mx0, __shfl_xor_sync(0xffffffffu, mx0, 2));
        mx1 = fmaxf(mx1, __shfl_xor_sync(0xffffffffu, mx1, 1));
        mx1 = fmaxf(mx1, __shfl_xor_sync(0xffffffffu, mx1, 2));
        float mn0 = fmaxf(m0, mx0), mn1 = fmaxf(m1, mx1);
        float a0 = exp2f(m0 - mn0), a1 = exp2f(m1 - mn1);
        m0 = mn0; m1 = mn1;

        float ls0 = 0.0f, ls1 = 0.0f;
        #pragma unroll
        for (int nt = 0; nt < 8; nt++) {
            sacc[nt][0] = exp2f(sacc[nt][0] - mn0);
            sacc[nt][1] = exp2f(sacc[nt][1] - mn0);
            sacc[nt][2] = exp2f(sacc[nt][2] - mn1);
            sacc[nt][3] = exp2f(sacc[nt][3] - mn1);
            ls0 += sacc[nt][0] + sacc[nt][1];
            ls1 += sacc[nt][2] + sacc[nt][3];
        }
        l0 = l0 * a0 + ls0;
        l1 = l1 * a1 + ls1;
        #pragma unroll
        for (int nt = 0; nt < 8; nt++) {
            oacc[nt][0] *= a0; oacc[nt][1] *= a0;
            oacc[nt][2] *= a1; oacc[nt][3] *= a1;
        }

        // ---- O += P @ V : P single fp16, V fp16 hi/lo ----
        #pragma unroll
        for (int kk = 0; kk < 4; kk++) {
            uint32_t ph[4], vf[4][4];
            ph[0] = pack_h2(sacc[2*kk  ][0], sacc[2*kk  ][1]);
            ph[1] = pack_h2(sacc[2*kk  ][2], sacc[2*kk  ][3]);
            ph[2] = pack_h2(sacc[2*kk+1][0], sacc[2*kk+1][1]);
            ph[3] = pack_h2(sacc[2*kk+1][2], sacc[2*kk+1][3]);
            // V_hi
            #pragma unroll
            for (int nd = 0; nd < 4; nd++)
                ldm_x4_t(vf[nd], va + kk * (16 * KSTR) + nd * 32);
            #pragma unroll
            for (int nd = 0; nd < 4; nd++) {
                uint32_t b0[2] = { vf[nd][0], vf[nd][1] };
                uint32_t b1[2] = { vf[nd][2], vf[nd][3] };
                mma16816h(oacc[2*nd+0], ph, b0);
                mma16816h(oacc[2*nd+1], ph, b1);
            }
            // V_lo
            #pragma unroll
            for (int nd = 0; nd < 4; nd++)
                ldm_x4_t(vf[nd], vaL + kk * (16 * KSTR) + nd * 32);
            #pragma unroll
            for (int nd = 0; nd < 4; nd++) {
                uint32_t b0[2] = { vf[nd][0], vf[nd][1] };
                uint32_t b1[2] = { vf[nd][2], vf[nd][3] };
                mma16816h(oacc[2*nd+0], ph, b0);
                mma16816h(oacc[2*nd+1], ph, b1);
            }
        }
    }

    // ---- finalize: normalize, fp16 hi/lo store (proj consumes directly) ----
    l0 += __shfl_xor_sync(0xffffffffu, l0, 1);
    l0 += __shfl_xor_sync(0xffffffffu, l0, 2);
    l1 += __shfl_xor_sync(0xffffffffu, l1, 1);
    l1 += __shfl_xor_sync(0xffffffffu, l1, 2);
    float inv0 = 1.0f / l0, inv1 = 1.0f / l1;

    const int g = lane >> 2, t = lane & 3;
    const int row = q0 + wid * 16 + g;
    size_t o0 = (size_t)(b * SEQ + row) * EMB + h * HD;
    size_t o1 = (size_t)(b * SEQ + row + 8) * EMB + h * HD;
    #pragma unroll
    for (int nt = 0; nt < 8; nt++) {
        int col = nt * 8 + t * 2;
        uint32_t h0, lo0, h1, lo1;
        split2h(oacc[nt][0] * inv0, oacc[nt][1] * inv0, h0, lo0);
        split2h(oacc[nt][2] * inv1, oacc[nt][3] * inv1, h1, lo1);
        *(uint32_t*)&atth[o0 + col] = h0;
        *(uint32_t*)&attl[o0 + col] = lo0;
        *(uint32_t*)&atth[o1 + col] = h1;
        *(uint32_t*)&attl[o1 + col] = lo1;
    }
}

// ---------------------------------------------------------------------------
extern "C" void kernel_launch(void* const* d_in, const int* in_sizes, int n_in,
                              void* d_out, int out_size)
{
    const float* x      = (const float*)d_in[0];
    const float* w_qkv  = (const float*)d_in[1];
    const float* b_qkv  = (const float*)d_in[2];
    const float* w_proj = (const float*)d_in[3];
    const float* b_proj = (const float*)d_in[4];
    float* out = (float*)d_out;

    __nv_bfloat16 *xh, *xl, *wq, *wp, *qh, *ql, *ath, *atl;
    cudaGetSymbolAddress((void**)&xh, g_xh);
    cudaGetSymbolAddress((void**)&xl, g_xl);
    cudaGetSymbolAddress((void**)&wq, g_wq);
    cudaGetSymbolAddress((void**)&wp, g_wp);
    cudaGetSymbolAddress((void**)&qh, g_qkvh);
    cudaGetSymbolAddress((void**)&ql, g_qkvl);
    cudaGetSymbolAddress((void**)&ath, g_atth);
    cudaGetSymbolAddress((void**)&atl, g_attl);

    cudaFuncSetAttribute(gemm_pre<true>,  cudaFuncAttributeMaxDynamicSharedMemorySize, GEMM_SMEM);
    cudaFuncSetAttribute(gemm_pre<false>, cudaFuncAttributeMaxDynamicSharedMemorySize, GEMM_SMEM);
    cudaFuncSetAttribute(attn_pre, cudaFuncAttributeMaxDynamicSharedMemorySize, ATT_SMEM);

    // 0) pre-convert operands: x -> fp16 hi/lo; weights -> fp16 single
    {
        int n4 = TOK * EMB / 4;
        split_f32h<<<(n4 + 255) / 256, 256>>>(x, xh, xl, n4);
        n4 = 3 * EMB * EMB / 4;
        cvt_f32h<<<(n4 + 255) / 256, 256>>>(w_qkv, wq, n4);
        n4 = EMB * EMB / 4;
        cvt_f32h<<<(n4 + 255) / 256, 256>>>(w_proj, wp, n4);
    }

    const float QSCALE = 0.125f * 1.4426950408889634f;   // 1/sqrt(64) * log2(e)

    // 1) QKV projection -> split qkv (Q scaled bf16, K bf16, V fp16)
    dim3 g1(3 * EMB / 128, TOK / 128);
    gemm_pre<true><<<g1, 256, GEMM_SMEM>>>(xh, xl, wq, b_qkv,
                                           nullptr, qh, ql,
                                           TOK, 3 * EMB, EMB, EMB, 2 * EMB, QSCALE);

    // 2) Attention -> fp16 hi/lo att
    dim3 g2(SEQ / 128, BATCH * NH);
    attn_pre<<<g2, 256, ATT_SMEM>>>(qh, ql, ath, atl);

    // 3) Output projection -> fp32 out
    dim3 g3(EMB / 128, TOK / 128);
    gemm_pre<false><<<g3, 256, GEMM_SMEM>>>(ath, atl, wp, b_proj,
                                            out, nullptr, nullptr,
                                            TOK, EMB, EMB, 0, 1 << 30, 1.0f);
}

// round 13
// speedup vs baseline: 1.6173x; 1.1187x over previous
#include <cuda_runtime.h>
#include <cuda_bf16.h>
#include <cuda_fp16.h>
#include <cstdint>

#define BATCH 4
#define SEQ   2048
#define EMB   1024
#define NH    16
#define HD    64
#define TOK   (BATCH*SEQ)      // 8192

// ---------------- scratch (device globals; 16-bit payloads, all fp16) ------
__device__ __nv_bfloat16 g_xh[(size_t)TOK * EMB];        // fp16 hi
__device__ __nv_bfloat16 g_xl[(size_t)TOK * EMB];        // fp16 lo
__device__ __nv_bfloat16 g_wq[(size_t)3 * EMB * EMB];    // fp16 (single)
__device__ __nv_bfloat16 g_wp[(size_t)EMB * EMB];        // fp16 (single)
__device__ __nv_bfloat16 g_qkvh[(size_t)TOK * 3 * EMB];  // fp16 hi (Q scaled)
__device__ __nv_bfloat16 g_qkvl[(size_t)TOK * 3 * EMB];  // fp16 lo
__device__ __nv_bfloat16 g_atth[(size_t)TOK * EMB];      // fp16 hi
__device__ __nv_bfloat16 g_attl[(size_t)TOK * EMB];      // fp16 lo

// ---------------- primitives ----------------
__device__ __forceinline__ uint32_t smem_u32(const void* p) {
    uint32_t a;
    asm("{ .reg .u64 t; cvta.to.shared.u64 t, %1; cvt.u32.u64 %0, t; }" : "=r"(a) : "l"(p));
    return a;
}
__device__ __forceinline__ void ldm_x4(uint32_t* r, uint32_t addr) {
    asm volatile("ldmatrix.sync.aligned.m8n8.x4.shared.b16 {%0,%1,%2,%3}, [%4];"
        : "=r"(r[0]), "=r"(r[1]), "=r"(r[2]), "=r"(r[3]) : "r"(addr));
}
__device__ __forceinline__ void ldm_x4_t(uint32_t* r, uint32_t addr) {
    asm volatile("ldmatrix.sync.aligned.m8n8.x4.trans.shared.b16 {%0,%1,%2,%3}, [%4];"
        : "=r"(r[0]), "=r"(r[1]), "=r"(r[2]), "=r"(r[3]) : "r"(addr));
}
__device__ __forceinline__ void mma16816h(float* c, const uint32_t* a, const uint32_t* b) {
    asm volatile(
        "mma.sync.aligned.m16n8k16.row.col.f32.f16.f16.f32 "
        "{%0,%1,%2,%3}, {%4,%5,%6,%7}, {%8,%9}, {%0,%1,%2,%3};"
        : "+f"(c[0]), "+f"(c[1]), "+f"(c[2]), "+f"(c[3])
        : "r"(a[0]), "r"(a[1]), "r"(a[2]), "r"(a[3]), "r"(b[0]), "r"(b[1]));
}
#define CP16(dst, src) \
    asm volatile("cp.async.cg.shared.global [%0], [%1], 16;" \
        :: "r"(dst), "l"(src) : "memory")
#define CP_COMMIT() asm volatile("cp.async.commit_group;" ::: "memory")
#define CP_WAIT0()  asm volatile("cp.async.wait_group 0;" ::: "memory")

// fp16 split: x = hi + lo exactly to ~2^-22
__device__ __forceinline__ void split2h(float x, float y, uint32_t& h, uint32_t& l) {
    __half2 hh = __floats2half2_rn(x, y);
    h = *(uint32_t*)&hh;
    float rx = __half2float(__low2half(hh)), ry = __half2float(__high2half(hh));
    __half2 ll = __floats2half2_rn(x - rx, y - ry);
    l = *(uint32_t*)&ll;
}
__device__ __forceinline__ uint32_t pack_h2(float x, float y) {
    __half2 h = __floats2half2_rn(x, y);
    return *(uint32_t*)&h;
}
__device__ __forceinline__ void cvt_splith(float4 v, uint2& hi, uint2& lo) {
    uint32_t h0, l0, h1, l1;
    split2h(v.x, v.y, h0, l0);
    split2h(v.z, v.w, h1, l1);
    hi.x = h0; hi.y = h1;
    lo.x = l0; lo.y = l1;
}

// ---------------- conversion kernels ----------------
__global__ void __launch_bounds__(256)
split_f32h(const float* __restrict__ in, __nv_bfloat16* __restrict__ h,
           __nv_bfloat16* __restrict__ l, int n4)
{
    int i = blockIdx.x * blockDim.x + threadIdx.x;
    if (i < n4) {
        float4 v = ((const float4*)in)[i];
        uint2 hi, lo;
        cvt_splith(v, hi, lo);
        ((uint2*)h)[i] = hi;
        ((uint2*)l)[i] = lo;
    }
}
__global__ void __launch_bounds__(256)
cvt_f32h(const float* __restrict__ in, __nv_bfloat16* __restrict__ h, int n4)
{
    int i = blockIdx.x * blockDim.x + threadIdx.x;
    if (i < n4) {
        float4 v = ((const float4*)in)[i];
        uint2 hi;
        hi.x = pack_h2(v.x, v.y);
        hi.y = pack_h2(v.z, v.w);
        ((uint2*)h)[i] = hi;
    }
}

// ======== fp16 2-term GEMM: C = (Ah+Al) x W16^T + bias (round-12, kept) ====
#define ROWB    80
#define PLANE_B (128 * ROWB)      // 10240
#define P_AH    0
#define P_AL    (1 * PLANE_B)
#define P_W     (2 * PLANE_B)
#define BUF_B   (3 * PLANE_B)     // 30720
#define GEMM_SMEM (2 * BUF_B)     // 61440 -> 2 CTAs/SM

__device__ __forceinline__ void mma_block_h(float acc[2][8][4],
        const uint32_t a[2][4], const uint32_t b[4][4]) {
    #pragma unroll
    for (int mt = 0; mt < 2; mt++)
        #pragma unroll
        for (int p = 0; p < 4; p++) {
            uint32_t b0[2] = { b[p][0], b[p][2] };
            uint32_t b1[2] = { b[p][1], b[p][3] };
            mma16816h(acc[mt][2*p+0], a[mt], b0);
            mma16816h(acc[mt][2*p+1], a[mt], b1);
        }
}

template<bool SPLIT_OUT>
__global__ void __launch_bounds__(256)
gemm_pre(const __nv_bfloat16* __restrict__ Ah, const __nv_bfloat16* __restrict__ Al,
         const __nv_bfloat16* __restrict__ W,
         const float* __restrict__ bias,
         float* __restrict__ Cf,
         __nv_bfloat16* __restrict__ Ch, __nv_bfloat16* __restrict__ Cl,
         int M, int N, int K, int qcols, float qscale)
{
    extern __shared__ __align__(128) char smem[];
    const uint32_t sb = smem_u32(smem);
    const int tid = threadIdx.x;
    const int lane = tid & 31, wid = tid >> 5;
    const int wm = wid >> 1, wn = wid & 1;
    const int m0 = blockIdx.y * 128;
    const int n0 = blockIdx.x * 128;

    float acc[2][8][4] = {};

    const int frow = lane & 15;
    const int fcol = ((lane >> 4) & 1) * 16;
    uint32_t a_addr[2], b_addr[4];
    #pragma unroll
    for (int mt = 0; mt < 2; mt++)
        a_addr[mt] = (uint32_t)((wm * 32 + mt * 16 + frow) * ROWB + fcol);
    #pragma unroll
    for (int p = 0; p < 4; p++)
        b_addr[p] = (uint32_t)((wn * 64 + p * 16 + frow) * ROWB + fcol);

    auto issue = [&](int stage, int k0) {
        const uint32_t sbuf = sb + stage * BUF_B;
        #pragma unroll
        for (int j = 0; j < 2; j++) {
            int cid = tid + j * 256;
            int r = cid >> 2, c16 = cid & 3;
            uint32_t so = (uint32_t)(r * ROWB + c16 * 16);
            size_t ga = (size_t)(m0 + r) * K + k0 + c16 * 8;
            size_t gb = (size_t)(n0 + r) * K + k0 + c16 * 8;
            CP16(sbuf + P_AH + so, Ah + ga);
            CP16(sbuf + P_AL + so, Al + ga);
            CP16(sbuf + P_W  + so, W  + gb);
        }
        CP_COMMIT();
    };

    const int nch = K / 32;
    issue(0, 0);

    for (int i = 0; i < nch; i++) {
        CP_WAIT0();
        __syncthreads();
        const uint32_t base = sb + (i & 1) * BUF_B;

        uint32_t a0h[2][4], a0l[2][4], b0[4][4];
        uint32_t a1h[2][4], a1l[2][4], b1[4][4];

        #pragma unroll
        for (int mt = 0; mt < 2; mt++) {
            ldm_x4(a0h[mt], base + P_AH + a_addr[mt]);
            ldm_x4(a0l[mt], base + P_AL + a_addr[mt]);
        }
        #pragma unroll
        for (int p = 0; p < 4; p++)
            ldm_x4(b0[p], base + P_W + b_addr[p]);

        if (i + 1 < nch) issue((i + 1) & 1, (i + 1) * 32);

        mma_block_h(acc, a0h, b0);     // hh(0)

        #pragma unroll
        for (int mt = 0; mt < 2; mt++) {
            ldm_x4(a1h[mt], base + P_AH + a_addr[mt] + 32);
            ldm_x4(a1l[mt], base + P_AL + a_addr[mt] + 32);
        }
        #pragma unroll
        for (int p = 0; p < 4; p++)
            ldm_x4(b1[p], base + P_W + b_addr[p] + 32);

        mma_block_h(acc, a0l, b0);     // lh(0)
        mma_block_h(acc, a1h, b1);     // hh(1)
        mma_block_h(acc, a1l, b1);     // lh(1)
    }

    // epilogue: all SPLIT_OUT columns fp16 hi/lo (Q cols pre-scaled)
    const int g = lane >> 2, t = lane & 3;
    #pragma unroll
    for (int mt = 0; mt < 2; mt++) {
        int row = m0 + wm * 32 + mt * 16 + g;
        #pragma unroll
        for (int nt = 0; nt < 8; nt++) {
            int col = n0 + wn * 64 + nt * 8 + t * 2;
            float bx = bias[col], by = bias[col + 1];
            float* c = acc[mt][nt];
            float v0 = c[0] + bx, v1 = c[1] + by;
            float v2 = c[2] + bx, v3 = c[3] + by;
            if (SPLIT_OUT) {
                float s = (col < qcols) ? qscale : 1.0f;
                uint32_t h0, l0, h1, l1;
                split2h(v0 * s, v1 * s, h0, l0);
                split2h(v2 * s, v3 * s, h1, l1);
                *(uint32_t*)&Ch[(size_t)row * N + col] = h0;
                *(uint32_t*)&Cl[(size_t)row * N + col] = l0;
                *(uint32_t*)&Ch[(size_t)(row + 8) * N + col] = h1;
                *(uint32_t*)&Cl[(size_t)(row + 8) * N + col] = l1;
            } else {
                *(float2*)(Cf + (size_t)row * N + col) = make_float2(v0, v1);
                *(float2*)(Cf + (size_t)(row + 8) * N + col) = make_float2(v2, v3);
            }
        }
    }
}

// ========== fp16 flash attention: 2-term S, 2-term PV, 3 KV planes =========
#define KSTR 144
#define KV_PL   (64 * KSTR)                  // 9216 per plane
#define KV_B    (3 * KV_PL)                  // 27648 per stage (Kh, Vh, Vl)
#define AQH 0
#define AQL (128 * KSTR)                     // 18432
#define AKV (2 * 128 * KSTR)                 // 36864
#define ATT_SMEM (AKV + 2 * KV_B)            // 92160 -> 2 CTAs/SM

__global__ void __launch_bounds__(256, 2)
attn_pre(const __nv_bfloat16* __restrict__ qkvh,
         const __nv_bfloat16* __restrict__ qkvl,
         __nv_bfloat16* __restrict__ atth,
         __nv_bfloat16* __restrict__ attl)
{
    extern __shared__ __align__(128) char smem[];
    const uint32_t sb = smem_u32(smem);
    const int tid = threadIdx.x;
    const int lane = tid & 31, wid = tid >> 5;
    const int b = blockIdx.y >> 4, h = blockIdx.y & 15;
    const int q0 = blockIdx.x * 128;

    const size_t rs = 3 * EMB;
    const __nv_bfloat16* Qh = qkvh + (size_t)(b * SEQ) * rs + h * HD;
    const __nv_bfloat16* Ql = qkvl + (size_t)(b * SEQ) * rs + h * HD;
    const __nv_bfloat16* Kh = Qh + EMB;          // fp16 hi (lo plane unused)
    const __nv_bfloat16* Vh = Qh + 2 * EMB;
    const __nv_bfloat16* Vl = Ql + 2 * EMB;

    auto issueKV = [&](int stage, int k0) {
        const uint32_t sbuf = sb + AKV + stage * KV_B;
        #pragma unroll
        for (int i = 0; i < 2; i++) {
            int idx = tid + i * 256;           // 0..511
            int r = idx >> 3, c16 = idx & 7;
            size_t go = (size_t)(k0 + r) * rs + c16 * 8;
            uint32_t so = (uint32_t)(r * KSTR + c16 * 16);
            CP16(sbuf + 0 * KV_PL + so, Kh + go);
            CP16(sbuf + 1 * KV_PL + so, Vh + go);
            CP16(sbuf + 2 * KV_PL + so, Vl + go);
        }
        CP_COMMIT();
    };

    issueKV(0, 0);

    // ---- load Q tile (sync; once) ----
    #pragma unroll
    for (int i = 0; i < 4; i++) {
        int idx = tid + i * 256;
        int r = idx >> 3, c16 = idx & 7;
        size_t go = (size_t)(q0 + r) * rs + c16 * 8;
        uint32_t so = r * KSTR + c16 * 16;
        *(uint4*)(smem + AQH + so) = *(const uint4*)(Qh + go);
        *(uint4*)(smem + AQL + so) = *(const uint4*)(Ql + go);
    }

    const int frow = lane & 15;
    const int fcol = ((lane >> 4) & 1) * 16;
    const uint32_t qa = sb + AQH + (uint32_t)((wid * 16 + frow) * KSTR + fcol);
    const uint32_t kvf = (uint32_t)(frow * KSTR + fcol);
    const uint32_t QLO = AQL - AQH;

    float oacc[8][4] = {};
    float m0 = -1e30f, m1 = -1e30f;
    float l0 = 0.0f, l1 = 0.0f;

    for (int kt = 0; kt < SEQ / 64; kt++) {
        CP_WAIT0();
        __syncthreads();
        if (kt + 1 < SEQ / 64) issueKV((kt + 1) & 1, (kt + 1) * 64);

        const uint32_t base = sb + AKV + (kt & 1) * KV_B;
        const uint32_t ka  = base + 0 * KV_PL + kvf;
        const uint32_t va  = base + 1 * KV_PL + kvf;
        const uint32_t vaL = base + 2 * KV_PL + kvf;

        // ---- S = (Qh+Ql) @ K16^T (16 x 64 per warp, fp16 2-term) ----
        float sacc[8][4] = {};
        #pragma unroll
        for (int kk = 0; kk < 4; kk++) {
            uint32_t aqh[4], aql[4], kf[4][4];
            ldm_x4(aqh, qa + kk * 32);
            ldm_x4(aql, qa + QLO + kk * 32);
            #pragma unroll
            for (int p = 0; p < 4; p++)
                ldm_x4(kf[p], ka + p * (16 * KSTR) + kk * 32);
            #pragma unroll
            for (int p = 0; p < 4; p++) {
                uint32_t b0[2] = { kf[p][0], kf[p][2] };
                uint32_t b1[2] = { kf[p][1], kf[p][3] };
                mma16816h(sacc[2*p+0], aqh, b0);
                mma16816h(sacc[2*p+1], aqh, b1);
            }
            #pragma unroll
            for (int p = 0; p < 4; p++) {
                uint32_t b0[2] = { kf[p][0], kf[p][2] };
                uint32_t b1[2] = { kf[p][1], kf[p][3] };
                mma16816h(sacc[2*p+0], aql, b0);
                mma16816h(sacc[2*p+1], aql, b1);
            }
        }

        // ---- online softmax (base-2, warp-local) ----
        float mx0 = -1e30f, mx1 = -1e30f;
        #pragma unroll
        for (int nt = 0; nt < 8; nt++) {
            mx0 = fmaxf(mx0, fmaxf(sacc[nt][0], sacc[nt][1]));
            mx1 = fmaxf(mx1, fmaxf(sacc[nt][2], sacc[nt][3]));
        }
        mx0 = fmaxf(mx0, __shfl_xor_sync(0xffffffffu, mx0, 1));
        mx0 = fmaxf(mx0, __shfl_xor_sync(0xffffffffu, mx0, 2));
        mx1 = fmaxf(mx1, __shfl_xor_sync(0xffffffffu, mx1, 1));
        mx1 = fmaxf(mx1, __shfl_xor_sync(0xffffffffu, mx1, 2));
        float mn0 = fmaxf(m0, mx0), mn1 = fmaxf(m1, mx1);
        float a0 = exp2f(m0 - mn0), a1 = exp2f(m1 - mn1);
        m0 = mn0; m1 = mn1;

        float ls0 = 0.0f, ls1 = 0.0f;
        #pragma unroll
        for (int nt = 0; nt < 8; nt++) {
            sacc[nt][0] = exp2f(sacc[nt][0] - mn0);
            sacc[nt][1] = exp2f(sacc[nt][1] - mn0);
            sacc[nt][2] = exp2f(sacc[nt][2] - mn1);
            sacc[nt][3] = exp2f(sacc[nt][3] - mn1);
            ls0 += sacc[nt][0] + sacc[nt][1];
            ls1 += sacc[nt][2] + sacc[nt][3];
        }
        l0 = l0 * a0 + ls0;
        l1 = l1 * a1 + ls1;
        #pragma unroll
        for (int nt = 0; nt < 8; nt++) {
            oacc[nt][0] *= a0; oacc[nt][1] *= a0;
            oacc[nt][2] *= a1; oacc[nt][3] *= a1;
        }

        // ---- O += P @ (Vh+Vl) : P single fp16 ----
        #pragma unroll
        for (int kk = 0; kk < 4; kk++) {
            uint32_t ph[4], vf[4][4];
            ph[0] = pack_h2(sacc[2*kk  ][0], sacc[2*kk  ][1]);
            ph[1] = pack_h2(sacc[2*kk  ][2], sacc[2*kk  ][3]);
            ph[2] = pack_h2(sacc[2*kk+1][0], sacc[2*kk+1][1]);
            ph[3] = pack_h2(sacc[2*kk+1][2], sacc[2*kk+1][3]);
            // V_hi
            #pragma unroll
            for (int nd = 0; nd < 4; nd++)
                ldm_x4_t(vf[nd], va + kk * (16 * KSTR) + nd * 32);
            #pragma unroll
            for (int nd = 0; nd < 4; nd++) {
                uint32_t b0[2] = { vf[nd][0], vf[nd][1] };
                uint32_t b1[2] = { vf[nd][2], vf[nd][3] };
                mma16816h(oacc[2*nd+0], ph, b0);
                mma16816h(oacc[2*nd+1], ph, b1);
            }
            // V_lo
            #pragma unroll
            for (int nd = 0; nd < 4; nd++)
                ldm_x4_t(vf[nd], vaL + kk * (16 * KSTR) + nd * 32);
            #pragma unroll
            for (int nd = 0; nd < 4; nd++) {
                uint32_t b0[2] = { vf[nd][0], vf[nd][1] };
                uint32_t b1[2] = { vf[nd][2], vf[nd][3] };
                mma16816h(oacc[2*nd+0], ph, b0);
                mma16816h(oacc[2*nd+1], ph, b1);
            }
        }
    }

    // ---- finalize: normalize, fp16 hi/lo store ----
    l0 += __shfl_xor_sync(0xffffffffu, l0, 1);
    l0 += __shfl_xor_sync(0xffffffffu, l0, 2);
    l1 += __shfl_xor_sync(0xffffffffu, l1, 1);
    l1 += __shfl_xor_sync(0xffffffffu, l1, 2);
    float inv0 = 1.0f / l0, inv1 = 1.0f / l1;

    const int g = lane >> 2, t = lane & 3;
    const int row = q0 + wid * 16 + g;
    size_t o0 = (size_t)(b * SEQ + row) * EMB + h * HD;
    size_t o1 = (size_t)(b * SEQ + row + 8) * EMB + h * HD;
    #pragma unroll
    for (int nt = 0; nt < 8; nt++) {
        int col = nt * 8 + t * 2;
        uint32_t h0, lo0, h1, lo1;
        split2h(oacc[nt][0] * inv0, oacc[nt][1] * inv0, h0, lo0);
        split2h(oacc[nt][2] * inv1, oacc[nt][3] * inv1, h1, lo1);
        *(uint32_t*)&atth[o0 + col] = h0;
        *(uint32_t*)&attl[o0 + col] = lo0;
        *(uint32_t*)&atth[o1 + col] = h1;
        *(uint32_t*)&attl[o1 + col] = lo1;
    }
}

// ---------------------------------------------------------------------------
extern "C" void kernel_launch(void* const* d_in, const int* in_sizes, int n_in,
                              void* d_out, int out_size)
{
    const float* x      = (const float*)d_in[0];
    const float* w_qkv  = (const float*)d_in[1];
    const float* b_qkv  = (const float*)d_in[2];
    const float* w_proj = (const float*)d_in[3];
    const float* b_proj = (const float*)d_in[4];
    float* out = (float*)d_out;

    __nv_bfloat16 *xh, *xl, *wq, *wp, *qh, *ql, *ath, *atl;
    cudaGetSymbolAddress((void**)&xh, g_xh);
    cudaGetSymbolAddress((void**)&xl, g_xl);
    cudaGetSymbolAddress((void**)&wq, g_wq);
    cudaGetSymbolAddress((void**)&wp, g_wp);
    cudaGetSymbolAddress((void**)&qh, g_qkvh);
    cudaGetSymbolAddress((void**)&ql, g_qkvl);
    cudaGetSymbolAddress((void**)&ath, g_atth);
    cudaGetSymbolAddress((void**)&atl, g_attl);

    cudaFuncSetAttribute(gemm_pre<true>,  cudaFuncAttributeMaxDynamicSharedMemorySize, GEMM_SMEM);
    cudaFuncSetAttribute(gemm_pre<false>, cudaFuncAttributeMaxDynamicSharedMemorySize, GEMM_SMEM);
    cudaFuncSetAttribute(attn_pre, cudaFuncAttributeMaxDynamicSharedMemorySize, ATT_SMEM);

    // 0) pre-convert operands: x -> fp16 hi/lo; weights -> fp16 single
    {
        int n4 = TOK * EMB / 4;
        split_f32h<<<(n4 + 255) / 256, 256>>>(x, xh, xl, n4);
        n4 = 3 * EMB * EMB / 4;
        cvt_f32h<<<(n4 + 255) / 256, 256>>>(w_qkv, wq, n4);
        n4 = EMB * EMB / 4;
        cvt_f32h<<<(n4 + 255) / 256, 256>>>(w_proj, wp, n4);
    }

    const float QSCALE = 0.125f * 1.4426950408889634f;   // 1/sqrt(64) * log2(e)

    // 1) QKV projection -> fp16 hi/lo qkv (Q cols pre-scaled)
    dim3 g1(3 * EMB / 128, TOK / 128);
    gemm_pre<true><<<g1, 256, GEMM_SMEM>>>(xh, xl, wq, b_qkv,
                                           nullptr, qh, ql,
                                           TOK, 3 * EMB, EMB, EMB, QSCALE);

    // 2) Attention -> fp16 hi/lo att
    dim3 g2(SEQ / 128, BATCH * NH);
    attn_pre<<<g2, 256, ATT_SMEM>>>(qh, ql, ath, atl);

    // 3) Output projection -> fp32 out
    dim3 g3(EMB / 128, TOK / 128);
    gemm_pre<false><<<g3, 256, GEMM_SMEM>>>(ath, atl, wp, b_proj,
                                            out, nullptr, nullptr,
                                            TOK, EMB, EMB, 0, 1.0f);
}

// round 14
// speedup vs baseline: 1.9264x; 1.1911x over previous
#include <cuda_runtime.h>
#include <cuda_bf16.h>
#include <cuda_fp16.h>
#include <cstdint>

#define BATCH 4
#define SEQ   2048
#define EMB   1024
#define NH    16
#define HD    64
#define TOK   (BATCH*SEQ)      // 8192

// ---------------- scratch (device globals; fp16 payloads) ----------
__device__ __nv_bfloat16 g_xh[(size_t)TOK * EMB];        // fp16 hi
__device__ __nv_bfloat16 g_xl[(size_t)TOK * EMB];        // fp16 lo
__device__ __nv_bfloat16 g_wq[(size_t)3 * EMB * EMB];    // fp16
__device__ __nv_bfloat16 g_wp[(size_t)EMB * EMB];        // fp16
__device__ __nv_bfloat16 g_qkvh[(size_t)TOK * 3 * EMB];  // fp16 hi (Q scaled)
__device__ __nv_bfloat16 g_qkvl[(size_t)TOK * 3 * EMB];  // fp16 lo (V region unused)
__device__ __nv_bfloat16 g_atth[(size_t)TOK * EMB];      // fp16 (single)

// ---------------- primitives ----------------
__device__ __forceinline__ uint32_t smem_u32(const void* p) {
    uint32_t a;
    asm("{ .reg .u64 t; cvta.to.shared.u64 t, %1; cvt.u32.u64 %0, t; }" : "=r"(a) : "l"(p));
    return a;
}
__device__ __forceinline__ void ldm_x4(uint32_t* r, uint32_t addr) {
    asm volatile("ldmatrix.sync.aligned.m8n8.x4.shared.b16 {%0,%1,%2,%3}, [%4];"
        : "=r"(r[0]), "=r"(r[1]), "=r"(r[2]), "=r"(r[3]) : "r"(addr));
}
__device__ __forceinline__ void ldm_x4_t(uint32_t* r, uint32_t addr) {
    asm volatile("ldmatrix.sync.aligned.m8n8.x4.trans.shared.b16 {%0,%1,%2,%3}, [%4];"
        : "=r"(r[0]), "=r"(r[1]), "=r"(r[2]), "=r"(r[3]) : "r"(addr));
}
__device__ __forceinline__ void mma16816h(float* c, const uint32_t* a, const uint32_t* b) {
    asm volatile(
        "mma.sync.aligned.m16n8k16.row.col.f32.f16.f16.f32 "
        "{%0,%1,%2,%3}, {%4,%5,%6,%7}, {%8,%9}, {%0,%1,%2,%3};"
        : "+f"(c[0]), "+f"(c[1]), "+f"(c[2]), "+f"(c[3])
        : "r"(a[0]), "r"(a[1]), "r"(a[2]), "r"(a[3]), "r"(b[0]), "r"(b[1]));
}
#define CP16(dst, src) \
    asm volatile("cp.async.cg.shared.global [%0], [%1], 16;" \
        :: "r"(dst), "l"(src) : "memory")
#define CP_COMMIT() asm volatile("cp.async.commit_group;" ::: "memory")
#define CP_WAIT0()  asm volatile("cp.async.wait_group 0;" ::: "memory")

// fp16 split: x = hi + lo exactly to ~2^-22
__device__ __forceinline__ void split2h(float x, float y, uint32_t& h, uint32_t& l) {
    __half2 hh = __floats2half2_rn(x, y);
    h = *(uint32_t*)&hh;
    float rx = __half2float(__low2half(hh)), ry = __half2float(__high2half(hh));
    __half2 ll = __floats2half2_rn(x - rx, y - ry);
    l = *(uint32_t*)&ll;
}
__device__ __forceinline__ uint32_t pack_h2(float x, float y) {
    __half2 h = __floats2half2_rn(x, y);
    return *(uint32_t*)&h;
}
__device__ __forceinline__ void cvt_splith(float4 v, uint2& hi, uint2& lo) {
    uint32_t h0, l0, h1, l1;
    split2h(v.x, v.y, h0, l0);
    split2h(v.z, v.w, h1, l1);
    hi.x = h0; hi.y = h1;
    lo.x = l0; lo.y = l1;
}

// ---------------- conversion kernels ----------------
__global__ void __launch_bounds__(256)
split_f32h(const float* __restrict__ in, __nv_bfloat16* __restrict__ h,
           __nv_bfloat16* __restrict__ l, int n4)
{
    int i = blockIdx.x * blockDim.x + threadIdx.x;
    if (i < n4) {
        float4 v = ((const float4*)in)[i];
        uint2 hi, lo;
        cvt_splith(v, hi, lo);
        ((uint2*)h)[i] = hi;
        ((uint2*)l)[i] = lo;
    }
}
__global__ void __launch_bounds__(256)
cvt_f32h(const float* __restrict__ in, __nv_bfloat16* __restrict__ h, int n4)
{
    int i = blockIdx.x * blockDim.x + threadIdx.x;
    if (i < n4) {
        float4 v = ((const float4*)in)[i];
        uint2 hi;
        hi.x = pack_h2(v.x, v.y);
        hi.y = pack_h2(v.z, v.w);
        ((uint2*)h)[i] = hi;
    }
}

// ======== fp16 GEMM: C = (Ah[+Al]) x W16^T + bias; TWO_TERM toggles Al ======
#define ROWB    80
#define PLANE_B (128 * ROWB)      // 10240
#define P_AH    0
#define P_AL    (1 * PLANE_B)
#define P_W     (2 * PLANE_B)
#define BUF_B   (3 * PLANE_B)     // 30720
#define GEMM_SMEM (2 * BUF_B)     // 61440 -> 2 CTAs/SM

__device__ __forceinline__ void mma_block_h(float acc[2][8][4],
        const uint32_t a[2][4], const uint32_t b[4][4]) {
    #pragma unroll
    for (int mt = 0; mt < 2; mt++)
        #pragma unroll
        for (int p = 0; p < 4; p++) {
            uint32_t b0[2] = { b[p][0], b[p][2] };
            uint32_t b1[2] = { b[p][1], b[p][3] };
            mma16816h(acc[mt][2*p+0], a[mt], b0);
            mma16816h(acc[mt][2*p+1], a[mt], b1);
        }
}

template<bool SPLIT_OUT, bool TWO_TERM>
__global__ void __launch_bounds__(256)
gemm_pre(const __nv_bfloat16* __restrict__ Ah, const __nv_bfloat16* __restrict__ Al,
         const __nv_bfloat16* __restrict__ W,
         const float* __restrict__ bias,
         float* __restrict__ Cf,
         __nv_bfloat16* __restrict__ Ch, __nv_bfloat16* __restrict__ Cl,
         int M, int N, int K, int qcols, float qscale)
{
    extern __shared__ __align__(128) char smem[];
    const uint32_t sb = smem_u32(smem);
    const int tid = threadIdx.x;
    const int lane = tid & 31, wid = tid >> 5;
    const int wm = wid >> 1, wn = wid & 1;
    const int m0 = blockIdx.y * 128;
    const int n0 = blockIdx.x * 128;

    float acc[2][8][4] = {};

    const int frow = lane & 15;
    const int fcol = ((lane >> 4) & 1) * 16;
    uint32_t a_addr[2], b_addr[4];
    #pragma unroll
    for (int mt = 0; mt < 2; mt++)
        a_addr[mt] = (uint32_t)((wm * 32 + mt * 16 + frow) * ROWB + fcol);
    #pragma unroll
    for (int p = 0; p < 4; p++)
        b_addr[p] = (uint32_t)((wn * 64 + p * 16 + frow) * ROWB + fcol);

    auto issue = [&](int stage, int k0) {
        const uint32_t sbuf = sb + stage * BUF_B;
        #pragma unroll
        for (int j = 0; j < 2; j++) {
            int cid = tid + j * 256;
            int r = cid >> 2, c16 = cid & 3;
            uint32_t so = (uint32_t)(r * ROWB + c16 * 16);
            size_t ga = (size_t)(m0 + r) * K + k0 + c16 * 8;
            size_t gb = (size_t)(n0 + r) * K + k0 + c16 * 8;
            CP16(sbuf + P_AH + so, Ah + ga);
            if (TWO_TERM) CP16(sbuf + P_AL + so, Al + ga);
            CP16(sbuf + P_W  + so, W  + gb);
        }
        CP_COMMIT();
    };

    const int nch = K / 32;
    issue(0, 0);

    for (int i = 0; i < nch; i++) {
        CP_WAIT0();
        __syncthreads();
        const uint32_t base = sb + (i & 1) * BUF_B;

        uint32_t a0h[2][4], a0l[2][4], b0[4][4];
        uint32_t a1h[2][4], a1l[2][4], b1[4][4];

        #pragma unroll
        for (int mt = 0; mt < 2; mt++) {
            ldm_x4(a0h[mt], base + P_AH + a_addr[mt]);
            if (TWO_TERM) ldm_x4(a0l[mt], base + P_AL + a_addr[mt]);
        }
        #pragma unroll
        for (int p = 0; p < 4; p++)
            ldm_x4(b0[p], base + P_W + b_addr[p]);

        if (i + 1 < nch) issue((i + 1) & 1, (i + 1) * 32);

        mma_block_h(acc, a0h, b0);                  // hh(0)

        #pragma unroll
        for (int mt = 0; mt < 2; mt++) {
            ldm_x4(a1h[mt], base + P_AH + a_addr[mt] + 32);
            if (TWO_TERM) ldm_x4(a1l[mt], base + P_AL + a_addr[mt] + 32);
        }
        #pragma unroll
        for (int p = 0; p < 4; p++)
            ldm_x4(b1[p], base + P_W + b_addr[p] + 32);

        if (TWO_TERM) mma_block_h(acc, a0l, b0);    // lh(0)
        mma_block_h(acc, a1h, b1);                  // hh(1)
        if (TWO_TERM) mma_block_h(acc, a1l, b1);    // lh(1)
    }

    // epilogue
    const int g = lane >> 2, t = lane & 3;
    #pragma unroll
    for (int mt = 0; mt < 2; mt++) {
        int row = m0 + wm * 32 + mt * 16 + g;
        #pragma unroll
        for (int nt = 0; nt < 8; nt++) {
            int col = n0 + wn * 64 + nt * 8 + t * 2;
            float bx = bias[col], by = bias[col + 1];
            float* c = acc[mt][nt];
            float v0 = c[0] + bx, v1 = c[1] + by;
            float v2 = c[2] + bx, v3 = c[3] + by;
            if (SPLIT_OUT) {
                float s = (col < qcols) ? qscale : 1.0f;
                uint32_t h0, l0, h1, l1;
                split2h(v0 * s, v1 * s, h0, l0);
                split2h(v2 * s, v3 * s, h1, l1);
                *(uint32_t*)&Ch[(size_t)row * N + col] = h0;
                *(uint32_t*)&Cl[(size_t)row * N + col] = l0;
                *(uint32_t*)&Ch[(size_t)(row + 8) * N + col] = h1;
                *(uint32_t*)&Cl[(size_t)(row + 8) * N + col] = l1;
            } else {
                *(float2*)(Cf + (size_t)row * N + col) = make_float2(v0, v1);
                *(float2*)(Cf + (size_t)(row + 8) * N + col) = make_float2(v2, v3);
            }
        }
    }
}

// ===== fp16 flash attention: 2-term S, 1-term PV (single-fp16 V), 2 planes ==
#define KSTR 144
#define KV_PL   (64 * KSTR)                  // 9216 per plane
#define KV_B    (2 * KV_PL)                  // 18432 per stage (Kh, Vh)
#define AQH 0
#define AQL (128 * KSTR)                     // 18432
#define AKV (2 * 128 * KSTR)                 // 36864
#define ATT_SMEM (AKV + 2 * KV_B)            // 73728 -> 2 CTAs/SM

__global__ void __launch_bounds__(256, 2)
attn_pre(const __nv_bfloat16* __restrict__ qkvh,
         const __nv_bfloat16* __restrict__ qkvl,
         __nv_bfloat16* __restrict__ atth)
{
    extern __shared__ __align__(128) char smem[];
    const uint32_t sb = smem_u32(smem);
    const int tid = threadIdx.x;
    const int lane = tid & 31, wid = tid >> 5;
    const int b = blockIdx.y >> 4, h = blockIdx.y & 15;
    const int q0 = blockIdx.x * 128;

    const size_t rs = 3 * EMB;
    const __nv_bfloat16* Qh = qkvh + (size_t)(b * SEQ) * rs + h * HD;
    const __nv_bfloat16* Ql = qkvl + (size_t)(b * SEQ) * rs + h * HD;
    const __nv_bfloat16* Kh = Qh + EMB;
    const __nv_bfloat16* Vh = Qh + 2 * EMB;

    auto issueKV = [&](int stage, int k0) {
        const uint32_t sbuf = sb + AKV + stage * KV_B;
        #pragma unroll
        for (int i = 0; i < 2; i++) {
            int idx = tid + i * 256;           // 0..511
            int r = idx >> 3, c16 = idx & 7;
            size_t go = (size_t)(k0 + r) * rs + c16 * 8;
            uint32_t so = (uint32_t)(r * KSTR + c16 * 16);
            CP16(sbuf + 0 * KV_PL + so, Kh + go);
            CP16(sbuf + 1 * KV_PL + so, Vh + go);
        }
        CP_COMMIT();
    };

    issueKV(0, 0);

    // ---- load Q tile (sync; once) ----
    #pragma unroll
    for (int i = 0; i < 4; i++) {
        int idx = tid + i * 256;
        int r = idx >> 3, c16 = idx & 7;
        size_t go = (size_t)(q0 + r) * rs + c16 * 8;
        uint32_t so = r * KSTR + c16 * 16;
        *(uint4*)(smem + AQH + so) = *(const uint4*)(Qh + go);
        *(uint4*)(smem + AQL + so) = *(const uint4*)(Ql + go);
    }

    const int frow = lane & 15;
    const int fcol = ((lane >> 4) & 1) * 16;
    const uint32_t qa = sb + AQH + (uint32_t)((wid * 16 + frow) * KSTR + fcol);
    const uint32_t kvf = (uint32_t)(frow * KSTR + fcol);
    const uint32_t QLO = AQL - AQH;

    float oacc[8][4] = {};
    float m0 = -1e30f, m1 = -1e30f;
    float l0 = 0.0f, l1 = 0.0f;

    for (int kt = 0; kt < SEQ / 64; kt++) {
        CP_WAIT0();
        __syncthreads();
        if (kt + 1 < SEQ / 64) issueKV((kt + 1) & 1, (kt + 1) * 64);

        const uint32_t base = sb + AKV + (kt & 1) * KV_B;
        const uint32_t ka = base + 0 * KV_PL + kvf;
        const uint32_t va = base + 1 * KV_PL + kvf;

        // ---- S = (Qh+Ql) @ K16^T (16 x 64 per warp, fp16 2-term) ----
        float sacc[8][4] = {};
        #pragma unroll
        for (int kk = 0; kk < 4; kk++) {
            uint32_t aqh[4], aql[4], kf[4][4];
            ldm_x4(aqh, qa + kk * 32);
            ldm_x4(aql, qa + QLO + kk * 32);
            #pragma unroll
            for (int p = 0; p < 4; p++)
                ldm_x4(kf[p], ka + p * (16 * KSTR) + kk * 32);
            #pragma unroll
            for (int p = 0; p < 4; p++) {
                uint32_t b0[2] = { kf[p][0], kf[p][2] };
                uint32_t b1[2] = { kf[p][1], kf[p][3] };
                mma16816h(sacc[2*p+0], aqh, b0);
                mma16816h(sacc[2*p+1], aqh, b1);
            }
            #pragma unroll
            for (int p = 0; p < 4; p++) {
                uint32_t b0[2] = { kf[p][0], kf[p][2] };
                uint32_t b1[2] = { kf[p][1], kf[p][3] };
                mma16816h(sacc[2*p+0], aql, b0);
                mma16816h(sacc[2*p+1], aql, b1);
            }
        }

        // ---- online softmax (base-2, warp-local) ----
        float mx0 = -1e30f, mx1 = -1e30f;
        #pragma unroll
        for (int nt = 0; nt < 8; nt++) {
            mx0 = fmaxf(mx0, fmaxf(sacc[nt][0], sacc[nt][1]));
            mx1 = fmaxf(mx1, fmaxf(sacc[nt][2], sacc[nt][3]));
        }
        mx0 = fmaxf(mx0, __shfl_xor_sync(0xffffffffu, mx0, 1));
        mx0 = fmaxf(mx0, __shfl_xor_sync(0xffffffffu, mx0, 2));
        mx1 = fmaxf(mx1, __shfl_xor_sync(0xffffffffu, mx1, 1));
        mx1 = fmaxf(mx1, __shfl_xor_sync(0xffffffffu, mx1, 2));
        float mn0 = fmaxf(m0, mx0), mn1 = fmaxf(m1, mx1);
        float a0 = exp2f(m0 - mn0), a1 = exp2f(m1 - mn1);
        m0 = mn0; m1 = mn1;

        float ls0 = 0.0f, ls1 = 0.0f;
        #pragma unroll
        for (int nt = 0; nt < 8; nt++) {
            sacc[nt][0] = exp2f(sacc[nt][0] - mn0);
            sacc[nt][1] = exp2f(sacc[nt][1] - mn0);
            sacc[nt][2] = exp2f(sacc[nt][2] - mn1);
            sacc[nt][3] = exp2f(sacc[nt][3] - mn1);
            ls0 += sacc[nt][0] + sacc[nt][1];
            ls1 += sacc[nt][2] + sacc[nt][3];
        }
        l0 = l0 * a0 + ls0;
        l1 = l1 * a1 + ls1;
        #pragma unroll
        for (int nt = 0; nt < 8; nt++) {
            oacc[nt][0] *= a0; oacc[nt][1] *= a0;
            oacc[nt][2] *= a1; oacc[nt][3] *= a1;
        }

        // ---- O += P @ V16 : single term ----
        #pragma unroll
        for (int kk = 0; kk < 4; kk++) {
            uint32_t ph[4], vf[4][4];
            ph[0] = pack_h2(sacc[2*kk  ][0], sacc[2*kk  ][1]);
            ph[1] = pack_h2(sacc[2*kk  ][2], sacc[2*kk  ][3]);
            ph[2] = pack_h2(sacc[2*kk+1][0], sacc[2*kk+1][1]);
            ph[3] = pack_h2(sacc[2*kk+1][2], sacc[2*kk+1][3]);
            #pragma unroll
            for (int nd = 0; nd < 4; nd++)
                ldm_x4_t(vf[nd], va + kk * (16 * KSTR) + nd * 32);
            #pragma unroll
            for (int nd = 0; nd < 4; nd++) {
                uint32_t b0[2] = { vf[nd][0], vf[nd][1] };
                uint32_t b1[2] = { vf[nd][2], vf[nd][3] };
                mma16816h(oacc[2*nd+0], ph, b0);
                mma16816h(oacc[2*nd+1], ph, b1);
            }
        }
    }

    // ---- finalize: normalize, single-fp16 store ----
    l0 += __shfl_xor_sync(0xffffffffu, l0, 1);
    l0 += __shfl_xor_sync(0xffffffffu, l0, 2);
    l1 += __shfl_xor_sync(0xffffffffu, l1, 1);
    l1 += __shfl_xor_sync(0xffffffffu, l1, 2);
    float inv0 = 1.0f / l0, inv1 = 1.0f / l1;

    const int g = lane >> 2, t = lane & 3;
    const int row = q0 + wid * 16 + g;
    size_t o0 = (size_t)(b * SEQ + row) * EMB + h * HD;
    size_t o1 = (size_t)(b * SEQ + row + 8) * EMB + h * HD;
    #pragma unroll
    for (int nt = 0; nt < 8; nt++) {
        int col = nt * 8 + t * 2;
        *(uint32_t*)&atth[o0 + col] = pack_h2(oacc[nt][0] * inv0, oacc[nt][1] * inv0);
        *(uint32_t*)&atth[o1 + col] = pack_h2(oacc[nt][2] * inv1, oacc[nt][3] * inv1);
    }
}

// ---------------------------------------------------------------------------
extern "C" void kernel_launch(void* const* d_in, const int* in_sizes, int n_in,
                              void* d_out, int out_size)
{
    const float* x      = (const float*)d_in[0];
    const float* w_qkv  = (const float*)d_in[1];
    const float* b_qkv  = (const float*)d_in[2];
    const float* w_proj = (const float*)d_in[3];
    const float* b_proj = (const float*)d_in[4];
    float* out = (float*)d_out;

    __nv_bfloat16 *xh, *xl, *wq, *wp, *qh, *ql, *ath;
    cudaGetSymbolAddress((void**)&xh, g_xh);
    cudaGetSymbolAddress((void**)&xl, g_xl);
    cudaGetSymbolAddress((void**)&wq, g_wq);
    cudaGetSymbolAddress((void**)&wp, g_wp);
    cudaGetSymbolAddress((void**)&qh, g_qkvh);
    cudaGetSymbolAddress((void**)&ql, g_qkvl);
    cudaGetSymbolAddress((void**)&ath, g_atth);

    cudaFuncSetAttribute((const void*)gemm_pre<true, true>,
                         cudaFuncAttributeMaxDynamicSharedMemorySize, GEMM_SMEM);
    cudaFuncSetAttribute((const void*)gemm_pre<false, false>,
                         cudaFuncAttributeMaxDynamicSharedMemorySize, GEMM_SMEM);
    cudaFuncSetAttribute(attn_pre, cudaFuncAttributeMaxDynamicSharedMemorySize, ATT_SMEM);

    // 0) pre-convert operands: x -> fp16 hi/lo; weights -> fp16 single
    {
        int n4 = TOK * EMB / 4;
        split_f32h<<<(n4 + 255) / 256, 256>>>(x, xh, xl, n4);
        n4 = 3 * EMB * EMB / 4;
        cvt_f32h<<<(n4 + 255) / 256, 256>>>(w_qkv, wq, n4);
        n4 = EMB * EMB / 4;
        cvt_f32h<<<(n4 + 255) / 256, 256>>>(w_proj, wp, n4);
    }

    const float QSCALE = 0.125f * 1.4426950408889634f;   // 1/sqrt(64) * log2(e)

    // 1) QKV projection (2-term) -> fp16 hi/lo qkv (Q cols pre-scaled)
    dim3 g1(3 * EMB / 128, TOK / 128);
    gemm_pre<true, true><<<g1, 256, GEMM_SMEM>>>(xh, xl, wq, b_qkv,
                                                 nullptr, qh, ql,
                                                 TOK, 3 * EMB, EMB, EMB, QSCALE);

    // 2) Attention -> single fp16 att
    dim3 g2(SEQ / 128, BATCH * NH);
    attn_pre<<<g2, 256, ATT_SMEM>>>(qh, ql, ath);

    // 3) Output projection (1-term) -> fp32 out
    dim3 g3(EMB / 128, TOK / 128);
    gemm_pre<false, false><<<g3, 256, GEMM_SMEM>>>(ath, nullptr, wp, b_proj,
                                                   out, nullptr, nullptr,
                                                   TOK, EMB, EMB, 0, 1.0f);
}

// round 15
// speedup vs baseline: 2.6887x; 1.3957x over previous
#include <cuda_runtime.h>
#include <cuda_bf16.h>
#include <cuda_fp16.h>
#include <cstdint>

#define BATCH 4
#define SEQ   2048
#define EMB   1024
#define NH    16
#define HD    64
#define TOK   (BATCH*SEQ)      // 8192

// ---------------- scratch (device globals; single fp16 everywhere) ---------
__device__ __nv_bfloat16 g_x16[(size_t)TOK * EMB];        // fp16
__device__ __nv_bfloat16 g_wq[(size_t)3 * EMB * EMB];     // fp16
__device__ __nv_bfloat16 g_wp[(size_t)EMB * EMB];         // fp16
__device__ __nv_bfloat16 g_qkv[(size_t)TOK * 3 * EMB];    // fp16 (Q scaled)
__device__ __nv_bfloat16 g_att[(size_t)TOK * EMB];        // fp16

// ---------------- primitives ----------------
__device__ __forceinline__ uint32_t smem_u32(const void* p) {
    uint32_t a;
    asm("{ .reg .u64 t; cvta.to.shared.u64 t, %1; cvt.u32.u64 %0, t; }" : "=r"(a) : "l"(p));
    return a;
}
__device__ __forceinline__ void ldm_x4(uint32_t* r, uint32_t addr) {
    asm volatile("ldmatrix.sync.aligned.m8n8.x4.shared.b16 {%0,%1,%2,%3}, [%4];"
        : "=r"(r[0]), "=r"(r[1]), "=r"(r[2]), "=r"(r[3]) : "r"(addr));
}
__device__ __forceinline__ void ldm_x4_t(uint32_t* r, uint32_t addr) {
    asm volatile("ldmatrix.sync.aligned.m8n8.x4.trans.shared.b16 {%0,%1,%2,%3}, [%4];"
        : "=r"(r[0]), "=r"(r[1]), "=r"(r[2]), "=r"(r[3]) : "r"(addr));
}
__device__ __forceinline__ void mma16816h(float* c, const uint32_t* a, const uint32_t* b) {
    asm volatile(
        "mma.sync.aligned.m16n8k16.row.col.f32.f16.f16.f32 "
        "{%0,%1,%2,%3}, {%4,%5,%6,%7}, {%8,%9}, {%0,%1,%2,%3};"
        : "+f"(c[0]), "+f"(c[1]), "+f"(c[2]), "+f"(c[3])
        : "r"(a[0]), "r"(a[1]), "r"(a[2]), "r"(a[3]), "r"(b[0]), "r"(b[1]));
}
#define CP16(dst, src) \
    asm volatile("cp.async.cg.shared.global [%0], [%1], 16;" \
        :: "r"(dst), "l"(src) : "memory")
#define CP_COMMIT() asm volatile("cp.async.commit_group;" ::: "memory")
#define CP_WAIT0()  asm volatile("cp.async.wait_group 0;" ::: "memory")

__device__ __forceinline__ uint32_t pack_h2(float x, float y) {
    __half2 h = __floats2half2_rn(x, y);
    return *(uint32_t*)&h;
}

// ---------------- conversion kernel (fp32 -> fp16) ----------------
__global__ void __launch_bounds__(256)
cvt_f32h(const float* __restrict__ in, __nv_bfloat16* __restrict__ h, int n4)
{
    int i = blockIdx.x * blockDim.x + threadIdx.x;
    if (i < n4) {
        float4 v = ((const float4*)in)[i];
        uint2 hi;
        hi.x = pack_h2(v.x, v.y);
        hi.y = pack_h2(v.z, v.w);
        ((uint2*)h)[i] = hi;
    }
}

// ======== fp16 1-term GEMM: C = A16 x W16^T + bias ========
#define ROWB    80
#define PLANE_B (128 * ROWB)      // 10240
#define P_A     0
#define P_W     (1 * PLANE_B)
#define BUF_B   (2 * PLANE_B)     // 20480
#define GEMM_SMEM (2 * BUF_B)     // 40960

__device__ __forceinline__ void mma_block_h(float acc[2][8][4],
        const uint32_t a[2][4], const uint32_t b[4][4]) {
    #pragma unroll
    for (int mt = 0; mt < 2; mt++)
        #pragma unroll
        for (int p = 0; p < 4; p++) {
            uint32_t b0[2] = { b[p][0], b[p][2] };
            uint32_t b1[2] = { b[p][1], b[p][3] };
            mma16816h(acc[mt][2*p+0], a[mt], b0);
            mma16816h(acc[mt][2*p+1], a[mt], b1);
        }
}

template<bool H16_OUT>
__global__ void __launch_bounds__(256)
gemm_pre(const __nv_bfloat16* __restrict__ A,
         const __nv_bfloat16* __restrict__ W,
         const float* __restrict__ bias,
         float* __restrict__ Cf,
         __nv_bfloat16* __restrict__ Ch,
         int M, int N, int K, int qcols, float qscale)
{
    extern __shared__ __align__(128) char smem[];
    const uint32_t sb = smem_u32(smem);
    const int tid = threadIdx.x;
    const int lane = tid & 31, wid = tid >> 5;
    const int wm = wid >> 1, wn = wid & 1;
    const int m0 = blockIdx.y * 128;
    const int n0 = blockIdx.x * 128;

    float acc[2][8][4] = {};

    const int frow = lane & 15;
    const int fcol = ((lane >> 4) & 1) * 16;
    uint32_t a_addr[2], b_addr[4];
    #pragma unroll
    for (int mt = 0; mt < 2; mt++)
        a_addr[mt] = (uint32_t)((wm * 32 + mt * 16 + frow) * ROWB + fcol);
    #pragma unroll
    for (int p = 0; p < 4; p++)
        b_addr[p] = (uint32_t)((wn * 64 + p * 16 + frow) * ROWB + fcol);

    auto issue = [&](int stage, int k0) {
        const uint32_t sbuf = sb + stage * BUF_B;
        #pragma unroll
        for (int j = 0; j < 2; j++) {
            int cid = tid + j * 256;
            int r = cid >> 2, c16 = cid & 3;
            uint32_t so = (uint32_t)(r * ROWB + c16 * 16);
            size_t ga = (size_t)(m0 + r) * K + k0 + c16 * 8;
            size_t gb = (size_t)(n0 + r) * K + k0 + c16 * 8;
            CP16(sbuf + P_A + so, A + ga);
            CP16(sbuf + P_W + so, W + gb);
        }
        CP_COMMIT();
    };

    const int nch = K / 32;
    issue(0, 0);

    for (int i = 0; i < nch; i++) {
        CP_WAIT0();
        __syncthreads();
        const uint32_t base = sb + (i & 1) * BUF_B;

        uint32_t a0[2][4], b0[4][4], a1[2][4], b1[4][4];

        #pragma unroll
        for (int mt = 0; mt < 2; mt++)
            ldm_x4(a0[mt], base + P_A + a_addr[mt]);
        #pragma unroll
        for (int p = 0; p < 4; p++)
            ldm_x4(b0[p], base + P_W + b_addr[p]);

        if (i + 1 < nch) issue((i + 1) & 1, (i + 1) * 32);

        // prefetch kh=1 under kh=0 MMAs
        #pragma unroll
        for (int mt = 0; mt < 2; mt++)
            ldm_x4(a1[mt], base + P_A + a_addr[mt] + 32);
        #pragma unroll
        for (int p = 0; p < 4; p++)
            ldm_x4(b1[p], base + P_W + b_addr[p] + 32);

        mma_block_h(acc, a0, b0);      // kh=0
        mma_block_h(acc, a1, b1);      // kh=1
    }

    // epilogue
    const int g = lane >> 2, t = lane & 3;
    #pragma unroll
    for (int mt = 0; mt < 2; mt++) {
        int row = m0 + wm * 32 + mt * 16 + g;
        #pragma unroll
        for (int nt = 0; nt < 8; nt++) {
            int col = n0 + wn * 64 + nt * 8 + t * 2;
            float bx = bias[col], by = bias[col + 1];
            float* c = acc[mt][nt];
            float v0 = c[0] + bx, v1 = c[1] + by;
            float v2 = c[2] + bx, v3 = c[3] + by;
            if (H16_OUT) {
                float s = (col < qcols) ? qscale : 1.0f;
                *(uint32_t*)&Ch[(size_t)row * N + col]       = pack_h2(v0 * s, v1 * s);
                *(uint32_t*)&Ch[(size_t)(row + 8) * N + col] = pack_h2(v2 * s, v3 * s);
            } else {
                *(float2*)(Cf + (size_t)row * N + col) = make_float2(v0, v1);
                *(float2*)(Cf + (size_t)(row + 8) * N + col) = make_float2(v2, v3);
            }
        }
    }
}

// ===== fp16 flash attention: 1-term S, 1-term PV, 2 KV planes/stage ========
#define KSTR 144
#define KV_PL   (64 * KSTR)                  // 9216 per plane
#define KV_B    (2 * KV_PL)                  // 18432 per stage (K, V)
#define AQ      0
#define AKV     (128 * KSTR)                 // 18432
#define ATT_SMEM (AKV + 2 * KV_B)            // 55296 -> 2 CTAs/SM (reg-bound)

__global__ void __launch_bounds__(256, 2)
attn_pre(const __nv_bfloat16* __restrict__ qkv,
         __nv_bfloat16* __restrict__ att)
{
    extern __shared__ __align__(128) char smem[];
    const uint32_t sb = smem_u32(smem);
    const int tid = threadIdx.x;
    const int lane = tid & 31, wid = tid >> 5;
    const int b = blockIdx.y >> 4, h = blockIdx.y & 15;
    const int q0 = blockIdx.x * 128;

    const size_t rs = 3 * EMB;
    const __nv_bfloat16* Qg = qkv + (size_t)(b * SEQ) * rs + h * HD;
    const __nv_bfloat16* Kg = Qg + EMB;
    const __nv_bfloat16* Vg = Qg + 2 * EMB;

    auto issueKV = [&](int stage, int k0) {
        const uint32_t sbuf = sb + AKV + stage * KV_B;
        #pragma unroll
        for (int i = 0; i < 2; i++) {
            int idx = tid + i * 256;           // 0..511
            int r = idx >> 3, c16 = idx & 7;
            size_t go = (size_t)(k0 + r) * rs + c16 * 8;
            uint32_t so = (uint32_t)(r * KSTR + c16 * 16);
            CP16(sbuf + 0 * KV_PL + so, Kg + go);
            CP16(sbuf + 1 * KV_PL + so, Vg + go);
        }
        CP_COMMIT();
    };

    issueKV(0, 0);

    // ---- load Q tile (sync; once) ----
    #pragma unroll
    for (int i = 0; i < 4; i++) {
        int idx = tid + i * 256;
        int r = idx >> 3, c16 = idx & 7;
        size_t go = (size_t)(q0 + r) * rs + c16 * 8;
        uint32_t so = r * KSTR + c16 * 16;
        *(uint4*)(smem + AQ + so) = *(const uint4*)(Qg + go);
    }

    const int frow = lane & 15;
    const int fcol = ((lane >> 4) & 1) * 16;
    const uint32_t qa = sb + AQ + (uint32_t)((wid * 16 + frow) * KSTR + fcol);
    const uint32_t kvf = (uint32_t)(frow * KSTR + fcol);

    float oacc[8][4] = {};
    float m0 = -1e30f, m1 = -1e30f;
    float l0 = 0.0f, l1 = 0.0f;

    for (int kt = 0; kt < SEQ / 64; kt++) {
        CP_WAIT0();
        __syncthreads();
        if (kt + 1 < SEQ / 64) issueKV((kt + 1) & 1, (kt + 1) * 64);

        const uint32_t base = sb + AKV + (kt & 1) * KV_B;
        const uint32_t ka = base + 0 * KV_PL + kvf;
        const uint32_t va = base + 1 * KV_PL + kvf;

        // ---- S = Q16 @ K16^T (16 x 64 per warp, 1-term) ----
        float sacc[8][4] = {};
        #pragma unroll
        for (int kk = 0; kk < 4; kk++) {
            uint32_t aq[4], kf[4][4];
            ldm_x4(aq, qa + kk * 32);
            #pragma unroll
            for (int p = 0; p < 4; p++)
                ldm_x4(kf[p], ka + p * (16 * KSTR) + kk * 32);
            #pragma unroll
            for (int p = 0; p < 4; p++) {
                uint32_t b0[2] = { kf[p][0], kf[p][2] };
                uint32_t b1[2] = { kf[p][1], kf[p][3] };
                mma16816h(sacc[2*p+0], aq, b0);
                mma16816h(sacc[2*p+1], aq, b1);
            }
        }

        // ---- online softmax (base-2, warp-local) ----
        float mx0 = -1e30f, mx1 = -1e30f;
        #pragma unroll
        for (int nt = 0; nt < 8; nt++) {
            mx0 = fmaxf(mx0, fmaxf(sacc[nt][0], sacc[nt][1]));
            mx1 = fmaxf(mx1, fmaxf(sacc[nt][2], sacc[nt][3]));
        }
        mx0 = fmaxf(mx0, __shfl_xor_sync(0xffffffffu, mx0, 1));
        mx0 = fmaxf(mx0, __shfl_xor_sync(0xffffffffu, mx0, 2));
        mx1 = fmaxf(mx1, __shfl_xor_sync(0xffffffffu, mx1, 1));
        mx1 = fmaxf(mx1, __shfl_xor_sync(0xffffffffu, mx1, 2));
        float mn0 = fmaxf(m0, mx0), mn1 = fmaxf(m1, mx1);
        float a0 = exp2f(m0 - mn0), a1 = exp2f(m1 - mn1);
        m0 = mn0; m1 = mn1;

        float ls0 = 0.0f, ls1 = 0.0f;
        #pragma unroll
        for (int nt = 0; nt < 8; nt++) {
            sacc[nt][0] = exp2f(sacc[nt][0] - mn0);
            sacc[nt][1] = exp2f(sacc[nt][1] - mn0);
            sacc[nt][2] = exp2f(sacc[nt][2] - mn1);
            sacc[nt][3] = exp2f(sacc[nt][3] - mn1);
            ls0 += sacc[nt][0] + sacc[nt][1];
            ls1 += sacc[nt][2] + sacc[nt][3];
        }
        l0 = l0 * a0 + ls0;
        l1 = l1 * a1 + ls1;
        #pragma unroll
        for (int nt = 0; nt < 8; nt++) {
            oacc[nt][0] *= a0; oacc[nt][1] *= a0;
            oacc[nt][2] *= a1; oacc[nt][3] *= a1;
        }

        // ---- O += P16 @ V16 (1-term) ----
        #pragma unroll
        for (int kk = 0; kk < 4; kk++) {
            uint32_t ph[4], vf[4][4];
            ph[0] = pack_h2(sacc[2*kk  ][0], sacc[2*kk  ][1]);
            ph[1] = pack_h2(sacc[2*kk  ][2], sacc[2*kk  ][3]);
            ph[2] = pack_h2(sacc[2*kk+1][0], sacc[2*kk+1][1]);
            ph[3] = pack_h2(sacc[2*kk+1][2], sacc[2*kk+1][3]);
            #pragma unroll
            for (int nd = 0; nd < 4; nd++)
                ldm_x4_t(vf[nd], va + kk * (16 * KSTR) + nd * 32);
            #pragma unroll
            for (int nd = 0; nd < 4; nd++) {
                uint32_t b0[2] = { vf[nd][0], vf[nd][1] };
                uint32_t b1[2] = { vf[nd][2], vf[nd][3] };
                mma16816h(oacc[2*nd+0], ph, b0);
                mma16816h(oacc[2*nd+1], ph, b1);
            }
        }
    }

    // ---- finalize: normalize, fp16 store ----
    l0 += __shfl_xor_sync(0xffffffffu, l0, 1);
    l0 += __shfl_xor_sync(0xffffffffu, l0, 2);
    l1 += __shfl_xor_sync(0xffffffffu, l1, 1);
    l1 += __shfl_xor_sync(0xffffffffu, l1, 2);
    float inv0 = 1.0f / l0, inv1 = 1.0f / l1;

    const int g = lane >> 2, t = lane & 3;
    const int row = q0 + wid * 16 + g;
    size_t o0 = (size_t)(b * SEQ + row) * EMB + h * HD;
    size_t o1 = (size_t)(b * SEQ + row + 8) * EMB + h * HD;
    #pragma unroll
    for (int nt = 0; nt < 8; nt++) {
        int col = nt * 8 + t * 2;
        *(uint32_t*)&att[o0 + col] = pack_h2(oacc[nt][0] * inv0, oacc[nt][1] * inv0);
        *(uint32_t*)&att[o1 + col] = pack_h2(oacc[nt][2] * inv1, oacc[nt][3] * inv1);
    }
}

// ---------------------------------------------------------------------------
extern "C" void kernel_launch(void* const* d_in, const int* in_sizes, int n_in,
                              void* d_out, int out_size)
{
    const float* x      = (const float*)d_in[0];
    const float* w_qkv  = (const float*)d_in[1];
    const float* b_qkv  = (const float*)d_in[2];
    const float* w_proj = (const float*)d_in[3];
    const float* b_proj = (const float*)d_in[4];
    float* out = (float*)d_out;

    __nv_bfloat16 *x16, *wq, *wp, *qkv, *att;
    cudaGetSymbolAddress((void**)&x16, g_x16);
    cudaGetSymbolAddress((void**)&wq, g_wq);
    cudaGetSymbolAddress((void**)&wp, g_wp);
    cudaGetSymbolAddress((void**)&qkv, g_qkv);
    cudaGetSymbolAddress((void**)&att, g_att);

    cudaFuncSetAttribute((const void*)gemm_pre<true>,
                         cudaFuncAttributeMaxDynamicSharedMemorySize, GEMM_SMEM);
    cudaFuncSetAttribute((const void*)gemm_pre<false>,
                         cudaFuncAttributeMaxDynamicSharedMemorySize, GEMM_SMEM);
    cudaFuncSetAttribute(attn_pre, cudaFuncAttributeMaxDynamicSharedMemorySize, ATT_SMEM);

    // 0) pre-convert operands to fp16
    {
        int n4 = TOK * EMB / 4;
        cvt_f32h<<<(n4 + 255) / 256, 256>>>(x, x16, n4);
        n4 = 3 * EMB * EMB / 4;
        cvt_f32h<<<(n4 + 255) / 256, 256>>>(w_qkv, wq, n4);
        n4 = EMB * EMB / 4;
        cvt_f32h<<<(n4 + 255) / 256, 256>>>(w_proj, wp, n4);
    }

    const float QSCALE = 0.125f * 1.4426950408889634f;   // 1/sqrt(64) * log2(e)

    // 1) QKV projection (1-term fp16) -> fp16 qkv (Q cols pre-scaled)
    dim3 g1(3 * EMB / 128, TOK / 128);
    gemm_pre<true><<<g1, 256, GEMM_SMEM>>>(x16, wq, b_qkv,
                                           nullptr, qkv,
                                           TOK, 3 * EMB, EMB, EMB, QSCALE);

    // 2) Attention (1-term S + 1-term PV) -> fp16 att
    dim3 g2(SEQ / 128, BATCH * NH);
    attn_pre<<<g2, 256, ATT_SMEM>>>(qkv, att);

    // 3) Output projection (1-term fp16) -> fp32 out
    dim3 g3(EMB / 128, TOK / 128);
    gemm_pre<false><<<g3, 256, GEMM_SMEM>>>(att, wp, b_proj,
                                            out, nullptr,
                                            TOK, EMB, EMB, 0, 1.0f);
}